// round 1
// baseline (speedup 1.0000x reference)
#include <cuda_runtime.h>
#include <math.h>

#define NN   20000
#define NE   320000
#define NE2  340000
#define NG   32
#define NH   8
#define HC   448
#define DIN  32
#define DE   5
#define NEG_SLOPE 0.2f
#define EPS_BN 1e-5f

// ---------------- scratch (static device arrays: no allocation) ----------------
__device__ float g_xl[NN * HC];
__device__ float g_xr[NN * HC];
__device__ float g_h [NN * HC];
__device__ float g_h2[NN * HC];
__device__ float g_loop[NN * DE];
__device__ float g_nsum[NN * DE];
__device__ int   g_deg[NN];
__device__ int   g_cs[NN + 1];
__device__ int   g_cur[NN];
__device__ int   g_eid[NE2];
__device__ float g_colsum[HC];
__device__ float g_colsq[HC];
__device__ float g_pooled[NG * HC];
__device__ float g_gcnt[NG];

// ---------------- zero accumulators ----------------
__global__ void k_zero() {
    int i = blockIdx.x * blockDim.x + threadIdx.x;
    int st = gridDim.x * blockDim.x;
    for (int j = i; j < NN; j += st) g_deg[j] = 0;
    for (int j = i; j < NN * DE; j += st) g_nsum[j] = 0.f;
    for (int j = i; j < HC; j += st) { g_colsum[j] = 0.f; g_colsq[j] = 0.f; }
    for (int j = i; j < NG * HC; j += st) g_pooled[j] = 0.f;
    for (int j = i; j < NG; j += st) g_gcnt[j] = 0.f;
}

// ---------------- self-loop attr: deg + edge_attr sums per dst ----------------
__global__ void k_selfloop_accum(const int* __restrict__ ei,
                                 const float* __restrict__ eattr) {
    int e = blockIdx.x * blockDim.x + threadIdx.x;
    if (e >= NE) return;
    int d = ei[NE + e];
    atomicAdd(&g_deg[d], 1);
#pragma unroll
    for (int j = 0; j < DE; j++)
        atomicAdd(&g_nsum[d * DE + j], eattr[e * DE + j]);
}

__global__ void k_loopattr() {
    int i = blockIdx.x * blockDim.x + threadIdx.x;
    if (i >= NN * DE) return;
    int n = i / DE;
    float dg = fmaxf((float)g_deg[n], 1.f);
    g_loop[i] = g_nsum[i] / dg;
}

// ---------------- exclusive scan over (deg+1) -> csr offsets (single block) ----------------
#define SCAN_T 1024
#define SCAN_CHUNK 20
__global__ void k_scan() {
    __shared__ int sums[SCAN_T];
    int t = threadIdx.x;
    int base = t * SCAN_CHUNK;
    int loc[SCAN_CHUNK];
    int s = 0;
#pragma unroll
    for (int i = 0; i < SCAN_CHUNK; i++) {
        int idx = base + i;
        int v = (idx < NN) ? (g_deg[idx] + 1) : 0;  // +1 self-loop
        loc[i] = s;
        s += v;
    }
    sums[t] = s;
    __syncthreads();
    for (int off = 1; off < SCAN_T; off <<= 1) {
        int v = (t >= off) ? sums[t - off] : 0;
        __syncthreads();
        sums[t] += v;
        __syncthreads();
    }
    int off0 = sums[t] - s;  // exclusive
#pragma unroll
    for (int i = 0; i < SCAN_CHUNK; i++) {
        int idx = base + i;
        if (idx < NN) { g_cs[idx] = off0 + loc[i]; g_cur[idx] = off0 + loc[i]; }
    }
    if (t == SCAN_T - 1) g_cs[NN] = sums[SCAN_T - 1];
}

// ---------------- scatter edge ids into CSR buckets ----------------
__global__ void k_scatter(const int* __restrict__ ei) {
    int e = blockIdx.x * blockDim.x + threadIdx.x;
    if (e >= NE2) return;
    int d = (e < NE) ? ei[NE + e] : (e - NE);
    int pos = atomicAdd(&g_cur[d], 1);
    g_eid[pos] = e;
}

// ---------------- tiled fp32 SGEMM: C[M,Nc] = A[M,K] @ B[K,Nc] ----------------
#define BM 128
#define BN 128
#define BK 8
__global__ __launch_bounds__(256) void sgemm(int M, int Nc, int K,
                                             const float* __restrict__ A,
                                             const float* __restrict__ B,
                                             float* __restrict__ C) {
    __shared__ float As[BK][BM];
    __shared__ float Bs[BK][BN];
    int tid = threadIdx.x;
    int tx = tid % 16, ty = tid / 16;
    int row0 = blockIdx.y * BM, col0 = blockIdx.x * BN;
    int arow = tid >> 1;           // 0..127
    int acol = (tid & 1) * 4;      // 0 or 4
    int brow = tid >> 5;           // 0..7
    int bcol = (tid & 31) * 4;     // 0..124
    float acc[8][8];
#pragma unroll
    for (int i = 0; i < 8; i++)
#pragma unroll
        for (int j = 0; j < 8; j++) acc[i][j] = 0.f;

    for (int k0 = 0; k0 < K; k0 += BK) {
        float4 av = make_float4(0.f, 0.f, 0.f, 0.f);
        int ar = row0 + arow;
        if (ar < M) av = *(const float4*)&A[(long)ar * K + k0 + acol];
        As[acol + 0][arow] = av.x; As[acol + 1][arow] = av.y;
        As[acol + 2][arow] = av.z; As[acol + 3][arow] = av.w;
        float4 bv = make_float4(0.f, 0.f, 0.f, 0.f);
        int bc = col0 + bcol;
        if (bc < Nc) bv = *(const float4*)&B[(long)(k0 + brow) * Nc + bc];
        Bs[brow][bcol + 0] = bv.x; Bs[brow][bcol + 1] = bv.y;
        Bs[brow][bcol + 2] = bv.z; Bs[brow][bcol + 3] = bv.w;
        __syncthreads();
#pragma unroll
        for (int k = 0; k < BK; k++) {
            float a[8], b[8];
            float4 a0 = *(const float4*)&As[k][ty * 8];
            float4 a1 = *(const float4*)&As[k][ty * 8 + 4];
            a[0]=a0.x;a[1]=a0.y;a[2]=a0.z;a[3]=a0.w;a[4]=a1.x;a[5]=a1.y;a[6]=a1.z;a[7]=a1.w;
            float4 b0 = *(const float4*)&Bs[k][tx * 8];
            float4 b1 = *(const float4*)&Bs[k][tx * 8 + 4];
            b[0]=b0.x;b[1]=b0.y;b[2]=b0.z;b[3]=b0.w;b[4]=b1.x;b[5]=b1.y;b[6]=b1.z;b[7]=b1.w;
#pragma unroll
            for (int i = 0; i < 8; i++)
#pragma unroll
                for (int j = 0; j < 8; j++) acc[i][j] += a[i] * b[j];
        }
        __syncthreads();
    }
#pragma unroll
    for (int i = 0; i < 8; i++) {
        int r = row0 + ty * 8 + i;
        if (r >= M) continue;
#pragma unroll
        for (int j = 0; j < 8; j += 4) {
            int c = col0 + tx * 8 + j;
            if (c < Nc) {
                float4 v = make_float4(acc[i][j], acc[i][j+1], acc[i][j+2], acc[i][j+3]);
                *(float4*)&C[(long)r * Nc + c] = v;
            }
        }
    }
}

// ---------------- fused GATv2 edge kernel: one block per dst node ----------------
// out[dst] = (sum_e w_e * xl[src_e]) / (sum_e w_e + 1e-16) + bias, optional ELU
// w_e,h = exp( sum_c att[h,c] * leaky_relu(xl[src]+xr[dst]+eattr@We, 0.2) )
__global__ __launch_bounds__(128) void k_gat(const float* __restrict__ xl,
                                             const float* __restrict__ xr,
                                             const float* __restrict__ We,
                                             const float* __restrict__ att,
                                             const float* __restrict__ bias,
                                             const float* __restrict__ eattr,
                                             const int* __restrict__ ei,
                                             float* __restrict__ out,
                                             int apply_elu) {
    __shared__ int   s_eid[1024];
    __shared__ float s_part[112];
    __shared__ float s_w[NH];
    __shared__ float s_wsum[NH];
    int dst = blockIdx.x;
    int t = threadIdx.x;
    int start = g_cs[dst];
    int deg = g_cs[dst + 1] - start;
    bool use_sm = (deg <= 1024);
    if (use_sm)
        for (int i = t; i < deg; i += 128) s_eid[i] = g_eid[start + i];
    if (t < NH) s_wsum[t] = 0.f;
    __syncthreads();
    if (use_sm && t == 0) {  // deterministic order: insertion sort (deg ~ 17)
        for (int i = 1; i < deg; i++) {
            int key = s_eid[i]; int j = i - 1;
            while (j >= 0 && s_eid[j] > key) { s_eid[j + 1] = s_eid[j]; j--; }
            s_eid[j + 1] = key;
        }
    }
    __syncthreads();

    bool act = (t < 112);
    int c0 = t * 4;
    int head = t / 14;   // 56 channels per head / 4 per thread
    float4 xr4 = make_float4(0,0,0,0), att4 = make_float4(0,0,0,0);
    float4 acc = make_float4(0,0,0,0);
    float4 We4[DE];
    if (act) {
        xr4 = *(const float4*)&xr[(long)dst * HC + c0];
        att4 = *(const float4*)&att[c0];
#pragma unroll
        for (int d = 0; d < DE; d++) We4[d] = *(const float4*)&We[d * HC + c0];
    }

    for (int i = 0; i < deg; i++) {
        int e = use_sm ? s_eid[i] : g_eid[start + i];
        float4 xl4 = make_float4(0,0,0,0);
        if (act) {
            int s; const float* ea;
            if (e < NE) { s = ei[e]; ea = eattr + (long)e * DE; }
            else        { s = e - NE; ea = g_loop + (long)dst * DE; }
            xl4 = *(const float4*)&xl[(long)s * HC + c0];
            float e0 = ea[0], e1 = ea[1], e2 = ea[2], e3 = ea[3], e4 = ea[4];
            float sx = xl4.x + xr4.x + e0*We4[0].x + e1*We4[1].x + e2*We4[2].x + e3*We4[3].x + e4*We4[4].x;
            float sy = xl4.y + xr4.y + e0*We4[0].y + e1*We4[1].y + e2*We4[2].y + e3*We4[3].y + e4*We4[4].y;
            float sz = xl4.z + xr4.z + e0*We4[0].z + e1*We4[1].z + e2*We4[2].z + e3*We4[3].z + e4*We4[4].z;
            float sw = xl4.w + xr4.w + e0*We4[0].w + e1*We4[1].w + e2*We4[2].w + e3*We4[3].w + e4*We4[4].w;
            sx = (sx > 0.f) ? sx : NEG_SLOPE * sx;
            sy = (sy > 0.f) ? sy : NEG_SLOPE * sy;
            sz = (sz > 0.f) ? sz : NEG_SLOPE * sz;
            sw = (sw > 0.f) ? sw : NEG_SLOPE * sw;
            s_part[t] = att4.x*sx + att4.y*sy + att4.z*sz + att4.w*sw;
        }
        __syncthreads();
        if (t < NH) {
            float sc = 0.f;
#pragma unroll
            for (int k = 0; k < 14; k++) sc += s_part[t * 14 + k];
            float w = expf(sc);
            s_w[t] = w;
            s_wsum[t] += w;
        }
        __syncthreads();
        if (act) {
            float w = s_w[head];
            acc.x += w * xl4.x; acc.y += w * xl4.y;
            acc.z += w * xl4.z; acc.w += w * xl4.w;
        }
    }
    if (act) {
        float inv = 1.f / (s_wsum[head] + 1e-16f);
        float4 b4 = *(const float4*)&bias[c0];
        float4 o;
        o.x = acc.x * inv + b4.x; o.y = acc.y * inv + b4.y;
        o.z = acc.z * inv + b4.z; o.w = acc.w * inv + b4.w;
        if (apply_elu) {
            o.x = (o.x > 0.f) ? o.x : expm1f(o.x);
            o.y = (o.y > 0.f) ? o.y : expm1f(o.y);
            o.z = (o.z > 0.f) ? o.z : expm1f(o.z);
            o.w = (o.w > 0.f) ? o.w : expm1f(o.w);
        }
        *(float4*)&out[(long)dst * HC + c0] = o;
    }
}

// ---------------- BatchNorm over N nodes ----------------
__global__ void k_bn_stats(const float* __restrict__ h) {
    int t = threadIdx.x;             // 448 threads, one per column
    int r0 = blockIdx.x * 64;
    int rend = min(r0 + 64, NN);
    float s = 0.f, q = 0.f;
    for (int r = r0; r < rend; r++) {
        float v = h[(long)r * HC + t];
        s += v; q += v * v;
    }
    atomicAdd(&g_colsum[t], s);
    atomicAdd(&g_colsq[t], q);
}

__global__ void k_bn_apply(const float* __restrict__ gamma,
                           const float* __restrict__ beta,
                           float* __restrict__ h) {
    int idx = blockIdx.x * blockDim.x + threadIdx.x;
    if (idx >= NN * HC / 4) return;
    int c0 = (idx * 4) % HC;
    float4 v = *(float4*)&h[idx * 4];
    float o[4] = {v.x, v.y, v.z, v.w};
#pragma unroll
    for (int k = 0; k < 4; k++) {
        int c = c0 + k;
        float m = g_colsum[c] * (1.f / NN);
        float var = g_colsq[c] * (1.f / NN) - m * m;
        float sc = rsqrtf(var + EPS_BN) * gamma[c];
        o[k] = (o[k] - m) * sc + beta[c];
    }
    *(float4*)&h[idx * 4] = make_float4(o[0], o[1], o[2], o[3]);
}

// ---------------- pooling ----------------
__global__ void k_gcount(const int* __restrict__ batch) {
    int i = blockIdx.x * blockDim.x + threadIdx.x;
    if (i < NN) atomicAdd(&g_gcnt[batch[i]], 1.f);
}

__global__ void k_pool_partial(const int* __restrict__ batch,
                               const float* __restrict__ h2) {
    int t = threadIdx.x;             // 448
    int r0 = blockIdx.x * 64;
    int rend = min(r0 + 64, NN);
    int g = -1; float acc = 0.f;
    for (int r = r0; r < rend; r++) {
        int bg = batch[r];
        if (bg != g) {
            if (g >= 0) atomicAdd(&g_pooled[g * HC + t], acc);
            g = bg; acc = 0.f;
        }
        acc += h2[(long)r * HC + t];
    }
    if (g >= 0) atomicAdd(&g_pooled[g * HC + t], acc);
}

// ---------------- final: mean, BN over 32 rows, linear(448->18), log_softmax ----------------
__global__ __launch_bounds__(512) void k_final(const float* __restrict__ gamma,
                                               const float* __restrict__ beta,
                                               const float* __restrict__ Wlin,
                                               const float* __restrict__ blin,
                                               float* __restrict__ out) {
    __shared__ float s_scale[HC];
    __shared__ float s_shift[HC];
    __shared__ float s_log[NG * 18];
    int t = threadIdx.x;
    for (int idx = t; idx < NG * HC; idx += 512) {
        int g = idx / HC;
        float c = fmaxf(g_gcnt[g], 1.f);
        g_pooled[idx] = g_pooled[idx] / c;
    }
    __syncthreads();
    if (t < HC) {
        float s = 0.f, q = 0.f;
        for (int g = 0; g < NG; g++) {
            float v = g_pooled[g * HC + t];
            s += v; q += v * v;
        }
        float m = s * (1.f / NG);
        float var = q * (1.f / NG) - m * m;
        float sc = rsqrtf(var + EPS_BN) * gamma[t];
        s_scale[t] = sc;
        s_shift[t] = beta[t] - m * sc;
    }
    __syncthreads();
    for (int o = t; o < NG * 18; o += 512) {
        int g = o / 18, j = o % 18;
        float acc = blin[j];
        for (int c = 0; c < HC; c++)
            acc += (g_pooled[g * HC + c] * s_scale[c] + s_shift[c]) * Wlin[c * 18 + j];
        s_log[o] = acc;
    }
    __syncthreads();
    if (t < NG) {
        float m = -1e30f;
        for (int j = 0; j < 18; j++) m = fmaxf(m, s_log[t * 18 + j]);
        float s = 0.f;
        for (int j = 0; j < 18; j++) s += expf(s_log[t * 18 + j] - m);
        float lse = m + logf(s);
        for (int j = 0; j < 18; j++) out[t * 18 + j] = s_log[t * 18 + j] - lse;
    }
}

// ---------------- host launcher ----------------
extern "C" void kernel_launch(void* const* d_in, const int* in_sizes, int n_in,
                              void* d_out, int out_size) {
    const float* x     = (const float*)d_in[0];
    const int*   ei    = (const int*)d_in[1];
    const float* eattr = (const float*)d_in[2];
    const int*   batch = (const int*)d_in[3];
    const float* Wl1   = (const float*)d_in[4];
    const float* Wr1   = (const float*)d_in[5];
    const float* We1   = (const float*)d_in[6];
    const float* att1  = (const float*)d_in[7];
    const float* bias1 = (const float*)d_in[8];
    const float* Wl2   = (const float*)d_in[9];
    const float* Wr2   = (const float*)d_in[10];
    const float* We2   = (const float*)d_in[11];
    const float* att2  = (const float*)d_in[12];
    const float* bias2 = (const float*)d_in[13];
    const float* gamma = (const float*)d_in[14];
    const float* beta  = (const float*)d_in[15];
    const float* Wlin  = (const float*)d_in[16];
    const float* blin  = (const float*)d_in[17];
    float* out = (float*)d_out;

    float *p_xl, *p_xr, *p_h, *p_h2;
    cudaGetSymbolAddress((void**)&p_xl, g_xl);
    cudaGetSymbolAddress((void**)&p_xr, g_xr);
    cudaGetSymbolAddress((void**)&p_h,  g_h);
    cudaGetSymbolAddress((void**)&p_h2, g_h2);

    k_zero<<<256, 256>>>();
    k_selfloop_accum<<<(NE + 255) / 256, 256>>>(ei, eattr);
    k_loopattr<<<(NN * DE + 255) / 256, 256>>>();
    k_scan<<<1, SCAN_T>>>();
    k_scatter<<<(NE2 + 255) / 256, 256>>>(ei);

    dim3 ggrid((HC + BN - 1) / BN, (NN + BM - 1) / BM);
    // layer 1
    sgemm<<<ggrid, 256>>>(NN, HC, DIN, x, Wl1, p_xl);
    sgemm<<<ggrid, 256>>>(NN, HC, DIN, x, Wr1, p_xr);
    k_gat<<<NN, 128>>>(p_xl, p_xr, We1, att1, bias1, eattr, ei, p_h, 1);
    // batchnorm
    k_bn_stats<<<(NN + 63) / 64, HC>>>(p_h);
    k_bn_apply<<<(NN * HC / 4 + 255) / 256, 256>>>(gamma, beta, p_h);
    // layer 2
    sgemm<<<ggrid, 256>>>(NN, HC, HC, p_h, Wl2, p_xl);
    sgemm<<<ggrid, 256>>>(NN, HC, HC, p_h, Wr2, p_xr);
    k_gat<<<NN, 128>>>(p_xl, p_xr, We2, att2, bias2, eattr, ei, p_h2, 0);
    // pool + head
    k_gcount<<<(NN + 255) / 256, 256>>>(batch);
    k_pool_partial<<<(NN + 63) / 64, HC>>>(batch, p_h2);
    k_final<<<1, 512>>>(gamma, beta, Wlin, blin, out);
}

// round 2
// speedup vs baseline: 1.5859x; 1.5859x over previous
#include <cuda_runtime.h>
#include <math.h>

#define NN   20000
#define NE   320000
#define NE2  340000
#define NG   32
#define NH   8
#define HC   448
#define DIN  32
#define DE   5
#define NEG_SLOPE 0.2f
#define EPS_BN 1e-5f

// ---------------- scratch (static device arrays: no allocation) ----------------
__device__ float g_xl[NN * HC];
__device__ float g_xr[NN * HC];
__device__ float g_h [NN * HC];
__device__ float g_h2[NN * HC];
__device__ float g_loop[NN * DE];
__device__ float g_nsum[NN * DE];
__device__ int   g_deg[NN];
__device__ int   g_cs[NN + 1];
__device__ int   g_cur[NN];
__device__ int   g_eid[NE2];
__device__ float g_colsum[HC];
__device__ float g_colsq[HC];
__device__ float g_pooled[NG * HC];
__device__ float g_gcnt[NG];
__device__ float g_wcat[HC * 2 * HC];   // concatenated [K][896] weights

// ---------------- zero accumulators ----------------
__global__ void k_zero() {
    int i = blockIdx.x * blockDim.x + threadIdx.x;
    int st = gridDim.x * blockDim.x;
    for (int j = i; j < NN; j += st) g_deg[j] = 0;
    for (int j = i; j < NN * DE; j += st) g_nsum[j] = 0.f;
    for (int j = i; j < HC; j += st) { g_colsum[j] = 0.f; g_colsq[j] = 0.f; }
    for (int j = i; j < NG * HC; j += st) g_pooled[j] = 0.f;
    for (int j = i; j < NG; j += st) g_gcnt[j] = 0.f;
}

// ---------------- self-loop attr: deg + edge_attr sums per dst ----------------
__global__ void k_selfloop_accum(const int* __restrict__ ei,
                                 const float* __restrict__ eattr) {
    int e = blockIdx.x * blockDim.x + threadIdx.x;
    if (e >= NE) return;
    int d = ei[NE + e];
    atomicAdd(&g_deg[d], 1);
#pragma unroll
    for (int j = 0; j < DE; j++)
        atomicAdd(&g_nsum[d * DE + j], eattr[e * DE + j]);
}

__global__ void k_loopattr() {
    int i = blockIdx.x * blockDim.x + threadIdx.x;
    if (i >= NN * DE) return;
    int n = i / DE;
    float dg = fmaxf((float)g_deg[n], 1.f);
    g_loop[i] = g_nsum[i] / dg;
}

// ---------------- exclusive scan over (deg+1) -> csr offsets (single block) ----------------
#define SCAN_T 1024
#define SCAN_CHUNK 20
__global__ void k_scan() {
    __shared__ int sums[SCAN_T];
    int t = threadIdx.x;
    int base = t * SCAN_CHUNK;
    int loc[SCAN_CHUNK];
    int s = 0;
#pragma unroll
    for (int i = 0; i < SCAN_CHUNK; i++) {
        int idx = base + i;
        int v = (idx < NN) ? (g_deg[idx] + 1) : 0;  // +1 self-loop
        loc[i] = s;
        s += v;
    }
    sums[t] = s;
    __syncthreads();
    for (int off = 1; off < SCAN_T; off <<= 1) {
        int v = (t >= off) ? sums[t - off] : 0;
        __syncthreads();
        sums[t] += v;
        __syncthreads();
    }
    int off0 = sums[t] - s;  // exclusive
#pragma unroll
    for (int i = 0; i < SCAN_CHUNK; i++) {
        int idx = base + i;
        if (idx < NN) { g_cs[idx] = off0 + loc[i]; g_cur[idx] = off0 + loc[i]; }
    }
    if (t == SCAN_T - 1) g_cs[NN] = sums[SCAN_T - 1];
}

// ---------------- scatter edge ids into CSR buckets ----------------
__global__ void k_scatter(const int* __restrict__ ei) {
    int e = blockIdx.x * blockDim.x + threadIdx.x;
    if (e >= NE2) return;
    int d = (e < NE) ? ei[NE + e] : (e - NE);
    int pos = atomicAdd(&g_cur[d], 1);
    g_eid[pos] = e;
}

// ---------------- weight concat: g_wcat[k][0:448]=Wl, [448:896]=Wr ----------------
__global__ void k_wcat(const float* __restrict__ Wl, const float* __restrict__ Wr, int K) {
    int i = blockIdx.x * blockDim.x + threadIdx.x;
    if (i >= K * HC) return;
    int k = i / HC, c = i % HC;
    g_wcat[k * (2 * HC) + c] = Wl[i];
    g_wcat[k * (2 * HC) + HC + c] = Wr[i];
}

// ---------------- tf32 tensor-core GEMM ----------------
// C[M, 896] = A[M, K] @ g_wcat[K, 896]; cols < 448 -> Cl, cols >= 448 -> Cr
__device__ __forceinline__ unsigned cvt_tf32(float x) {
    unsigned u;
    asm("cvt.rna.tf32.f32 %0, %1;" : "=r"(u) : "f"(x));
    return u;
}

__device__ __forceinline__ void mma_tf32(float* c, const unsigned* a, const unsigned* b) {
    asm volatile(
        "mma.sync.aligned.m16n8k8.row.col.f32.tf32.tf32.f32 "
        "{%0,%1,%2,%3}, {%4,%5,%6,%7}, {%8,%9}, {%0,%1,%2,%3};\n"
        : "+f"(c[0]), "+f"(c[1]), "+f"(c[2]), "+f"(c[3])
        : "r"(a[0]), "r"(a[1]), "r"(a[2]), "r"(a[3]), "r"(b[0]), "r"(b[1]));
}

#define GNC 896
__global__ __launch_bounds__(256) void gemm_tf32(
    int M, int K,
    const float* __restrict__ A, const float* __restrict__ W,
    float* __restrict__ Cl, float* __restrict__ Cr)
{
    __shared__ unsigned As[2][128][20];  // [m][k], pitch 20 -> conflict-free frags
    __shared__ unsigned Bs[2][16][72];   // [k][n], pitch 72 -> conflict-free frags
    const int tid = threadIdx.x;
    const int lane = tid & 31, wid = tid >> 5;
    const int wm = wid & 3, wn = wid >> 2;
    const int row0 = blockIdx.y * 128, col0 = blockIdx.x * 64;

    float acc[2][4][4];
#pragma unroll
    for (int i = 0; i < 2; i++)
#pragma unroll
        for (int j = 0; j < 4; j++)
#pragma unroll
            for (int r = 0; r < 4; r++) acc[i][j][r] = 0.f;

    const int a_r = tid >> 2;           // 0..63
    const int a_c = (tid & 3) * 4;      // 0,4,8,12
    const int b_r = tid >> 4;           // 0..15
    const int b_c = (tid & 15) * 4;     // 0..60

    uint4 sa[2]; uint4 sb;
    const int nit = K / 16;

    // prologue: load iter 0
    {
        int k0 = 0;
#pragma unroll
        for (int p = 0; p < 2; p++) {
            int r = row0 + a_r + p * 64;
            float4 v = make_float4(0.f, 0.f, 0.f, 0.f);
            if (r < M) v = *(const float4*)&A[(size_t)r * K + k0 + a_c];
            sa[p] = make_uint4(cvt_tf32(v.x), cvt_tf32(v.y), cvt_tf32(v.z), cvt_tf32(v.w));
        }
        float4 w = *(const float4*)&W[(size_t)(k0 + b_r) * GNC + col0 + b_c];
        sb = make_uint4(cvt_tf32(w.x), cvt_tf32(w.y), cvt_tf32(w.z), cvt_tf32(w.w));
#pragma unroll
        for (int p = 0; p < 2; p++)
            *(uint4*)&As[0][a_r + p * 64][a_c] = sa[p];
        *(uint4*)&Bs[0][b_r][b_c] = sb;
    }
    __syncthreads();

    for (int it = 0; it < nit; ++it) {
        int cur = it & 1;
        if (it + 1 < nit) {
            int k0 = (it + 1) * 16;
#pragma unroll
            for (int p = 0; p < 2; p++) {
                int r = row0 + a_r + p * 64;
                float4 v = make_float4(0.f, 0.f, 0.f, 0.f);
                if (r < M) v = *(const float4*)&A[(size_t)r * K + k0 + a_c];
                sa[p] = make_uint4(cvt_tf32(v.x), cvt_tf32(v.y), cvt_tf32(v.z), cvt_tf32(v.w));
            }
            float4 w = *(const float4*)&W[(size_t)(k0 + b_r) * GNC + col0 + b_c];
            sb = make_uint4(cvt_tf32(w.x), cvt_tf32(w.y), cvt_tf32(w.z), cvt_tf32(w.w));
        }
#pragma unroll
        for (int ks = 0; ks < 2; ks++) {
            int kb = ks * 8;
            unsigned af[2][4], bf[4][2];
#pragma unroll
            for (int mi = 0; mi < 2; mi++) {
                int mb = wm * 32 + mi * 16;
                af[mi][0] = As[cur][mb + (lane >> 2)][kb + (lane & 3)];
                af[mi][1] = As[cur][mb + 8 + (lane >> 2)][kb + (lane & 3)];
                af[mi][2] = As[cur][mb + (lane >> 2)][kb + 4 + (lane & 3)];
                af[mi][3] = As[cur][mb + 8 + (lane >> 2)][kb + 4 + (lane & 3)];
            }
#pragma unroll
            for (int ni = 0; ni < 4; ni++) {
                int nb = wn * 32 + ni * 8;
                bf[ni][0] = Bs[cur][kb + (lane & 3)][nb + (lane >> 2)];
                bf[ni][1] = Bs[cur][kb + 4 + (lane & 3)][nb + (lane >> 2)];
            }
#pragma unroll
            for (int mi = 0; mi < 2; mi++)
#pragma unroll
                for (int ni = 0; ni < 4; ni++)
                    mma_tf32(acc[mi][ni], af[mi], bf[ni]);
        }
        if (it + 1 < nit) {
#pragma unroll
            for (int p = 0; p < 2; p++)
                *(uint4*)&As[1 - cur][a_r + p * 64][a_c] = sa[p];
            *(uint4*)&Bs[1 - cur][b_r][b_c] = sb;
            __syncthreads();
        }
    }

    // epilogue: split columns into Cl / Cr
#pragma unroll
    for (int mi = 0; mi < 2; mi++) {
#pragma unroll
        for (int ni = 0; ni < 4; ni++) {
            int rA = row0 + wm * 32 + mi * 16 + (lane >> 2);
            int cg = col0 + wn * 32 + ni * 8 + (lane & 3) * 2;
            float* base = (cg < HC) ? Cl : Cr;
            int cc = (cg < HC) ? cg : cg - HC;
            if (rA < M)
                *(float2*)&base[(size_t)rA * HC + cc] =
                    make_float2(acc[mi][ni][0], acc[mi][ni][1]);
            int rB = rA + 8;
            if (rB < M)
                *(float2*)&base[(size_t)rB * HC + cc] =
                    make_float2(acc[mi][ni][2], acc[mi][ni][3]);
        }
    }
}

// ---------------- fused GATv2 edge kernel: barrier-free, shuffle reductions ----------------
// 128 threads = 8 head-groups of 16 lanes (half-warps); lanes 0..13 active (14*4=56 ch)
__global__ __launch_bounds__(128) void k_gat(const float* __restrict__ xl,
                                             const float* __restrict__ xr,
                                             const float* __restrict__ We,
                                             const float* __restrict__ att,
                                             const float* __restrict__ bias,
                                             const float* __restrict__ eattr,
                                             const int* __restrict__ ei,
                                             float* __restrict__ out,
                                             int apply_elu) {
    __shared__ int s_eid[1024];
    __shared__ int s_srt[1024];
    int dst = blockIdx.x;
    int t = threadIdx.x;
    int start = g_cs[dst];
    int deg = g_cs[dst + 1] - start;
    for (int i = t; i < deg; i += 128) s_eid[i] = g_eid[start + i];
    __syncthreads();
    // parallel rank sort (keys unique): deterministic accumulation order
    for (int i = t; i < deg; i += 128) {
        int key = s_eid[i]; int r = 0;
        for (int j = 0; j < deg; j++) r += (s_eid[j] < key);
        s_srt[r] = key;
    }
    __syncthreads();

    int g = t >> 4, l = t & 15;
    bool act = (l < 14);
    int c0 = g * 56 + l * 4;
    float4 xr4 = make_float4(0,0,0,0), att4 = make_float4(0,0,0,0);
    float4 We4[DE];
    float4 acc = make_float4(0,0,0,0);
    float wsum = 0.f;
    if (act) {
        xr4 = *(const float4*)&xr[(size_t)dst * HC + c0];
        att4 = *(const float4*)&att[c0];
#pragma unroll
        for (int d = 0; d < DE; d++) We4[d] = *(const float4*)&We[d * HC + c0];
    }

    for (int i = 0; i < deg; i++) {
        int e = s_srt[i];
        float partial = 0.f;
        float4 xl4 = make_float4(0,0,0,0);
        if (act) {
            int s; const float* ea;
            if (e < NE) { s = ei[e]; ea = eattr + (size_t)e * DE; }
            else        { s = dst;   ea = g_loop + (size_t)dst * DE; }
            xl4 = *(const float4*)&xl[(size_t)s * HC + c0];
            float e0 = ea[0], e1 = ea[1], e2 = ea[2], e3 = ea[3], e4 = ea[4];
            float sx = xl4.x + xr4.x + e0*We4[0].x + e1*We4[1].x + e2*We4[2].x + e3*We4[3].x + e4*We4[4].x;
            float sy = xl4.y + xr4.y + e0*We4[0].y + e1*We4[1].y + e2*We4[2].y + e3*We4[3].y + e4*We4[4].y;
            float sz = xl4.z + xr4.z + e0*We4[0].z + e1*We4[1].z + e2*We4[2].z + e3*We4[3].z + e4*We4[4].z;
            float sw = xl4.w + xr4.w + e0*We4[0].w + e1*We4[1].w + e2*We4[2].w + e3*We4[3].w + e4*We4[4].w;
            sx = (sx > 0.f) ? sx : NEG_SLOPE * sx;
            sy = (sy > 0.f) ? sy : NEG_SLOPE * sy;
            sz = (sz > 0.f) ? sz : NEG_SLOPE * sz;
            sw = (sw > 0.f) ? sw : NEG_SLOPE * sw;
            partial = att4.x*sx + att4.y*sy + att4.z*sz + att4.w*sw;
        }
        // reduce over 16-lane group (stays within half-warp)
        partial += __shfl_xor_sync(0xffffffffu, partial, 8);
        partial += __shfl_xor_sync(0xffffffffu, partial, 4);
        partial += __shfl_xor_sync(0xffffffffu, partial, 2);
        partial += __shfl_xor_sync(0xffffffffu, partial, 1);
        float w = expf(partial);
        if (act) {
            wsum += w;
            acc.x += w * xl4.x; acc.y += w * xl4.y;
            acc.z += w * xl4.z; acc.w += w * xl4.w;
        }
    }
    if (act) {
        float inv = 1.f / (wsum + 1e-16f);
        float4 b4 = *(const float4*)&bias[c0];
        float4 o;
        o.x = acc.x * inv + b4.x; o.y = acc.y * inv + b4.y;
        o.z = acc.z * inv + b4.z; o.w = acc.w * inv + b4.w;
        if (apply_elu) {
            o.x = (o.x > 0.f) ? o.x : expm1f(o.x);
            o.y = (o.y > 0.f) ? o.y : expm1f(o.y);
            o.z = (o.z > 0.f) ? o.z : expm1f(o.z);
            o.w = (o.w > 0.f) ? o.w : expm1f(o.w);
        }
        *(float4*)&out[(size_t)dst * HC + c0] = o;
    }
}

// ---------------- BatchNorm over N nodes ----------------
__global__ void k_bn_stats(const float* __restrict__ h) {
    int t = threadIdx.x;             // 448 threads, one per column
    int r0 = blockIdx.x * 64;
    int rend = min(r0 + 64, NN);
    float s = 0.f, q = 0.f;
    for (int r = r0; r < rend; r++) {
        float v = h[(size_t)r * HC + t];
        s += v; q += v * v;
    }
    atomicAdd(&g_colsum[t], s);
    atomicAdd(&g_colsq[t], q);
}

__global__ void k_bn_apply(const float* __restrict__ gamma,
                           const float* __restrict__ beta,
                           float* __restrict__ h) {
    int idx = blockIdx.x * blockDim.x + threadIdx.x;
    if (idx >= NN * HC / 4) return;
    int c0 = (idx * 4) % HC;
    float4 v = *(float4*)&h[idx * 4];
    float o[4] = {v.x, v.y, v.z, v.w};
#pragma unroll
    for (int k = 0; k < 4; k++) {
        int c = c0 + k;
        float m = g_colsum[c] * (1.f / NN);
        float var = g_colsq[c] * (1.f / NN) - m * m;
        float sc = rsqrtf(var + EPS_BN) * gamma[c];
        o[k] = (o[k] - m) * sc + beta[c];
    }
    *(float4*)&h[idx * 4] = make_float4(o[0], o[1], o[2], o[3]);
}

// ---------------- pooling ----------------
__global__ void k_gcount(const int* __restrict__ batch) {
    int i = blockIdx.x * blockDim.x + threadIdx.x;
    if (i < NN) atomicAdd(&g_gcnt[batch[i]], 1.f);
}

__global__ void k_pool_partial(const int* __restrict__ batch,
                               const float* __restrict__ h2) {
    int t = threadIdx.x;             // 448
    int r0 = blockIdx.x * 64;
    int rend = min(r0 + 64, NN);
    int g = -1; float acc = 0.f;
    for (int r = r0; r < rend; r++) {
        int bg = batch[r];
        if (bg != g) {
            if (g >= 0) atomicAdd(&g_pooled[g * HC + t], acc);
            g = bg; acc = 0.f;
        }
        acc += h2[(size_t)r * HC + t];
    }
    if (g >= 0) atomicAdd(&g_pooled[g * HC + t], acc);
}

// ---------------- final: mean, BN over 32 rows, linear(448->18), log_softmax ----------------
__global__ __launch_bounds__(512) void k_final(const float* __restrict__ gamma,
                                               const float* __restrict__ beta,
                                               const float* __restrict__ Wlin,
                                               const float* __restrict__ blin,
                                               float* __restrict__ out) {
    __shared__ float s_scale[HC];
    __shared__ float s_shift[HC];
    __shared__ float s_log[NG * 18];
    int t = threadIdx.x;
    for (int idx = t; idx < NG * HC; idx += 512) {
        int g = idx / HC;
        float c = fmaxf(g_gcnt[g], 1.f);
        g_pooled[idx] = g_pooled[idx] / c;
    }
    __syncthreads();
    if (t < HC) {
        float s = 0.f, q = 0.f;
        for (int g = 0; g < NG; g++) {
            float v = g_pooled[g * HC + t];
            s += v; q += v * v;
        }
        float m = s * (1.f / NG);
        float var = q * (1.f / NG) - m * m;
        float sc = rsqrtf(var + EPS_BN) * gamma[t];
        s_scale[t] = sc;
        s_shift[t] = beta[t] - m * sc;
    }
    __syncthreads();
    for (int o = t; o < NG * 18; o += 512) {
        int g = o / 18, j = o % 18;
        float acc = blin[j];
        for (int c = 0; c < HC; c++)
            acc += (g_pooled[g * HC + c] * s_scale[c] + s_shift[c]) * Wlin[c * 18 + j];
        s_log[o] = acc;
    }
    __syncthreads();
    if (t < NG) {
        float m = -1e30f;
        for (int j = 0; j < 18; j++) m = fmaxf(m, s_log[t * 18 + j]);
        float s = 0.f;
        for (int j = 0; j < 18; j++) s += expf(s_log[t * 18 + j] - m);
        float lse = m + logf(s);
        for (int j = 0; j < 18; j++) out[t * 18 + j] = s_log[t * 18 + j] - lse;
    }
}

// ---------------- host launcher ----------------
extern "C" void kernel_launch(void* const* d_in, const int* in_sizes, int n_in,
                              void* d_out, int out_size) {
    const float* x     = (const float*)d_in[0];
    const int*   ei    = (const int*)d_in[1];
    const float* eattr = (const float*)d_in[2];
    const int*   batch = (const int*)d_in[3];
    const float* Wl1   = (const float*)d_in[4];
    const float* Wr1   = (const float*)d_in[5];
    const float* We1   = (const float*)d_in[6];
    const float* att1  = (const float*)d_in[7];
    const float* bias1 = (const float*)d_in[8];
    const float* Wl2   = (const float*)d_in[9];
    const float* Wr2   = (const float*)d_in[10];
    const float* We2   = (const float*)d_in[11];
    const float* att2  = (const float*)d_in[12];
    const float* bias2 = (const float*)d_in[13];
    const float* gamma = (const float*)d_in[14];
    const float* beta  = (const float*)d_in[15];
    const float* Wlin  = (const float*)d_in[16];
    const float* blin  = (const float*)d_in[17];
    float* out = (float*)d_out;

    float *p_xl, *p_xr, *p_h, *p_h2, *p_wcat;
    cudaGetSymbolAddress((void**)&p_xl, g_xl);
    cudaGetSymbolAddress((void**)&p_xr, g_xr);
    cudaGetSymbolAddress((void**)&p_h,  g_h);
    cudaGetSymbolAddress((void**)&p_h2, g_h2);
    cudaGetSymbolAddress((void**)&p_wcat, g_wcat);

    k_zero<<<256, 256>>>();
    k_selfloop_accum<<<(NE + 255) / 256, 256>>>(ei, eattr);
    k_loopattr<<<(NN * DE + 255) / 256, 256>>>();
    k_scan<<<1, SCAN_T>>>();
    k_scatter<<<(NE2 + 255) / 256, 256>>>(ei);

    dim3 ggrid(GNC / 64, (NN + 127) / 128);
    // layer 1
    k_wcat<<<(DIN * HC + 255) / 256, 256>>>(Wl1, Wr1, DIN);
    gemm_tf32<<<ggrid, 256>>>(NN, DIN, x, p_wcat, p_xl, p_xr);
    k_gat<<<NN, 128>>>(p_xl, p_xr, We1, att1, bias1, eattr, ei, p_h, 1);
    // batchnorm
    k_bn_stats<<<(NN + 63) / 64, HC>>>(p_h);
    k_bn_apply<<<(NN * HC / 4 + 255) / 256, 256>>>(gamma, beta, p_h);
    // layer 2
    k_wcat<<<(HC * HC + 255) / 256, 256>>>(Wl2, Wr2, HC);
    gemm_tf32<<<ggrid, 256>>>(NN, HC, p_h, p_wcat, p_xl, p_xr);
    k_gat<<<NN, 128>>>(p_xl, p_xr, We2, att2, bias2, eattr, ei, p_h2, 0);
    // pool + head
    k_gcount<<<(NN + 255) / 256, 256>>>(batch);
    k_pool_partial<<<(NN + 63) / 64, HC>>>(batch, p_h2);
    k_final<<<1, 512>>>(gamma, beta, Wlin, blin, out);
}

// round 10
// speedup vs baseline: 1.8013x; 1.1358x over previous
#include <cuda_runtime.h>
#include <cuda_fp16.h>
#include <cstdint>
#include <cstddef>
#include <math.h>

#define NN   20000
#define NE   320000
#define NE2  340000
#define NG   32
#define NH   8
#define HC   448
#define DIN  32
#define DE   5
#define NEG_SLOPE 0.2f
#define EPS_BN 1e-5f

// ---------------- scratch (static device arrays: no allocation) ----------------
__device__ float g_xl[NN * HC];
__device__ float g_xr[NN * HC];
__device__ float g_h [NN * HC];
__device__ float g_h2[NN * HC];
__device__ float g_loop[NN * DE];
__device__ int   g_deg[NN];
__device__ int   g_cs[NN + 1];
__device__ int   g_cur[NN];
__device__ int   g_eid[NE2];
__device__ float g_colsum[HC];
__device__ float g_colsq[HC];
__device__ float g_pooled[NG * HC];
__device__ float g_gcnt[NG];
__device__ float g_scale[HC];
__device__ float g_shift[HC];
__device__ int   g_bsum[128];
__device__ int   g_boff[128];
__device__ __half g_af16[NN * HC];        // A in fp16, [NN][K]
__device__ __half g_wt16[2 * HC * HC];    // W^T in fp16, [896][K]

// ---------------- zero accumulators ----------------
__global__ void k_zero() {
    int i = blockIdx.x * blockDim.x + threadIdx.x;
    int st = gridDim.x * blockDim.x;
    for (int j = i; j < NN; j += st) g_deg[j] = 0;
    for (int j = i; j < HC; j += st) { g_colsum[j] = 0.f; g_colsq[j] = 0.f; }
    for (int j = i; j < NG * HC; j += st) g_pooled[j] = 0.f;
    for (int j = i; j < NG; j += st) g_gcnt[j] = 0.f;
}

// ---------------- degree ----------------
__global__ void k_deg(const int* __restrict__ ei) {
    int e = blockIdx.x * blockDim.x + threadIdx.x;
    if (e < NE) atomicAdd(&g_deg[ei[NE + e]], 1);
}

// ---------------- 3-kernel parallel exclusive scan of (deg+1) ----------------
#define SB 256
#define NBLK 79
__global__ void k_scan1() {
    int b = blockIdx.x, t = threadIdx.x;
    int idx = b * SB + t;
    int v = (idx < NN) ? g_deg[idx] + 1 : 0;
    int s = v;
#pragma unroll
    for (int o = 16; o >= 1; o >>= 1) s += __shfl_xor_sync(0xffffffffu, s, o);
    __shared__ int ws[8];
    if ((t & 31) == 0) ws[t >> 5] = s;
    __syncthreads();
    if (t == 0) {
        int tot = 0;
#pragma unroll
        for (int w = 0; w < 8; w++) tot += ws[w];
        g_bsum[b] = tot;
    }
}
__global__ void k_scan2() {
    __shared__ int sv[128];
    int t = threadIdx.x;
    int v = (t < NBLK) ? g_bsum[t] : 0;
    sv[t] = v;
    __syncthreads();
    for (int off = 1; off < 128; off <<= 1) {
        int u = (t >= off) ? sv[t - off] : 0;
        __syncthreads();
        sv[t] += u;
        __syncthreads();
    }
    if (t < NBLK) g_boff[t] = sv[t] - v;   // exclusive
    if (t == NBLK - 1) g_cs[NN] = sv[t];   // total
}
__global__ void k_scan3() {
    int b = blockIdx.x, t = threadIdx.x;
    int lane = t & 31, wid = t >> 5;
    int idx = b * SB + t;
    int v = (idx < NN) ? g_deg[idx] + 1 : 0;
    int inc = v;
#pragma unroll
    for (int o = 1; o < 32; o <<= 1) {
        int u = __shfl_up_sync(0xffffffffu, inc, o);
        if (lane >= o) inc += u;
    }
    __shared__ int ws[8];
    if (lane == 31) ws[wid] = inc;
    __syncthreads();
    if (wid == 0 && lane < 8) {
        int wv = ws[lane];
#pragma unroll
        for (int o = 1; o < 8; o <<= 1) {
            int u = __shfl_up_sync(0xffu, wv, o);
            if (lane >= o) wv += u;
        }
        ws[lane] = wv;
    }
    __syncthreads();
    int base = g_boff[b] + (wid > 0 ? ws[wid - 1] : 0);
    int ex = base + inc - v;
    if (idx < NN) { g_cs[idx] = ex; g_cur[idx] = ex; }
}

// ---------------- scatter edge ids into CSR buckets ----------------
__global__ void k_scatter(const int* __restrict__ ei) {
    int e = blockIdx.x * blockDim.x + threadIdx.x;
    if (e >= NE2) return;
    int d = (e < NE) ? ei[NE + e] : (e - NE);
    int pos = atomicAdd(&g_cur[d], 1);
    g_eid[pos] = e;
}

// ---------------- self-loop attr via CSR: one warp per node ----------------
__global__ void k_loopattr_csr(const float* __restrict__ eattr) {
    int w = blockIdx.x * 8 + (threadIdx.x >> 5);
    int lane = threadIdx.x & 31;
    if (w >= NN) return;
    int s0 = g_cs[w];
    int n = g_cs[w + 1] - s0;
    float a0 = 0.f, a1 = 0.f, a2 = 0.f, a3 = 0.f, a4 = 0.f;
    for (int i = lane; i < n; i += 32) {
        int e = g_eid[s0 + i];
        if (e < NE) {
            const float* p = eattr + (size_t)e * DE;
            a0 += p[0]; a1 += p[1]; a2 += p[2]; a3 += p[3]; a4 += p[4];
        }
    }
#pragma unroll
    for (int o = 16; o >= 1; o >>= 1) {
        a0 += __shfl_xor_sync(0xffffffffu, a0, o);
        a1 += __shfl_xor_sync(0xffffffffu, a1, o);
        a2 += __shfl_xor_sync(0xffffffffu, a2, o);
        a3 += __shfl_xor_sync(0xffffffffu, a3, o);
        a4 += __shfl_xor_sync(0xffffffffu, a4, o);
    }
    if (lane == 0) {
        float dg = fmaxf((float)g_deg[w], 1.f);
        g_loop[w * DE + 0] = a0 / dg;
        g_loop[w * DE + 1] = a1 / dg;
        g_loop[w * DE + 2] = a2 / dg;
        g_loop[w * DE + 3] = a3 / dg;
        g_loop[w * DE + 4] = a4 / dg;
    }
}

// ---------------- weight prep: W^T -> fp16, [896][K] ----------------
__global__ void k_prep_w(const float* __restrict__ Wl, const float* __restrict__ Wr, int K) {
    int i = blockIdx.x * blockDim.x + threadIdx.x;
    if (i >= 2 * HC * K) return;
    int n = i / K, k = i % K;
    float v = (n < HC) ? Wl[k * HC + n] : Wr[k * HC + (n - HC)];
    g_wt16[i] = __float2half(v);
}

// ---------------- A prep layer1: x -> fp16, [NN][32] ----------------
__global__ void k_prep_a1(const float* __restrict__ x) {
    int i = blockIdx.x * blockDim.x + threadIdx.x;
    if (i < NN * DIN) g_af16[i] = __float2half(x[i]);
}

// ---------------- A prep layer2: BN(h) fused -> fp16 ----------------
__global__ void k_prep_a2() {
    int i = blockIdx.x * blockDim.x + threadIdx.x;
    if (i >= NN * HC) return;
    int c = i % HC;
    g_af16[i] = __float2half(g_h[i] * g_scale[c] + g_shift[c]);
}

// ======================= fp16 mma.sync GEMM =======================
// C[NN, 896] = A[NN, K] @ W[K, 896]; W^T given as [896][K] fp16.
// BM=128, BN=128, BK=32; 256 threads = 8 warps (4 x 2), warp tile 32x64.
#define BM 128
#define BN 128
#define BK 32
#define APITCH 40   // halves: conflict-free (banks (20r+t) mod 32 distinct)

__device__ __forceinline__ void mma16816(float* c, const uint32_t* a, const uint32_t* b) {
    asm volatile(
        "mma.sync.aligned.m16n8k16.row.col.f32.f16.f16.f32 "
        "{%0,%1,%2,%3}, {%4,%5,%6,%7}, {%8,%9}, {%0,%1,%2,%3};\n"
        : "+f"(c[0]), "+f"(c[1]), "+f"(c[2]), "+f"(c[3])
        : "r"(a[0]), "r"(a[1]), "r"(a[2]), "r"(a[3]), "r"(b[0]), "r"(b[1]));
}

__global__ __launch_bounds__(256) void gemm_f16(int K,
                                                const __half* __restrict__ A,
                                                const __half* __restrict__ W,
                                                float* __restrict__ Cl,
                                                float* __restrict__ Cr) {
    __shared__ __half As[2][BM][APITCH];
    __shared__ __half Bs[2][BN][APITCH];
    const int tid = threadIdx.x, lane = tid & 31, wid = tid >> 5;
    const int wm = wid & 3, wn = wid >> 2;       // 4 x 2 warp grid
    const int g = lane >> 2, tg = lane & 3;
    const int m0 = blockIdx.y * BM, n0 = blockIdx.x * BN;
    const int nit = K / BK;

    float acc[2][8][4];
#pragma unroll
    for (int mi = 0; mi < 2; mi++)
#pragma unroll
        for (int ni = 0; ni < 8; ni++)
#pragma unroll
            for (int r = 0; r < 4; r++) acc[mi][ni][r] = 0.f;

    // load mapping: 128 rows x 4 segs of 16B; two groups per thread
    const int lr0 = tid >> 2, seg = tid & 3;     // rows lr0 and lr0+64

    uint4 sa[2], sb[2];
    // prologue: kc0 = 0
    {
#pragma unroll
        for (int p = 0; p < 2; p++) {
            int r = m0 + lr0 + p * 64;
            sa[p] = make_uint4(0u, 0u, 0u, 0u);
            if (r < NN) sa[p] = *(const uint4*)(A + (size_t)r * K + seg * 8);
            sb[p] = *(const uint4*)(W + (size_t)(n0 + lr0 + p * 64) * K + seg * 8);
        }
#pragma unroll
        for (int p = 0; p < 2; p++) {
            *(uint4*)&As[0][lr0 + p * 64][seg * 8] = sa[p];
            *(uint4*)&Bs[0][lr0 + p * 64][seg * 8] = sb[p];
        }
    }
    __syncthreads();

    for (int it = 0; it < nit; ++it) {
        int cur = it & 1;
        if (it + 1 < nit) {
            int kc0 = (it + 1) * BK;
#pragma unroll
            for (int p = 0; p < 2; p++) {
                int r = m0 + lr0 + p * 64;
                sa[p] = make_uint4(0u, 0u, 0u, 0u);
                if (r < NN) sa[p] = *(const uint4*)(A + (size_t)r * K + kc0 + seg * 8);
                sb[p] = *(const uint4*)(W + (size_t)(n0 + lr0 + p * 64) * K + kc0 + seg * 8);
            }
        }
#pragma unroll
        for (int ks = 0; ks < 2; ks++) {
            int kb = ks * 16;
            uint32_t af[2][4], bf[8][2];
#pragma unroll
            for (int mi = 0; mi < 2; mi++) {
                int mr = wm * 32 + mi * 16 + g;
                af[mi][0] = *(const uint32_t*)&As[cur][mr][kb + 2 * tg];
                af[mi][1] = *(const uint32_t*)&As[cur][mr + 8][kb + 2 * tg];
                af[mi][2] = *(const uint32_t*)&As[cur][mr][kb + 2 * tg + 8];
                af[mi][3] = *(const uint32_t*)&As[cur][mr + 8][kb + 2 * tg + 8];
            }
#pragma unroll
            for (int ni = 0; ni < 8; ni++) {
                int nc = wn * 64 + ni * 8 + g;
                bf[ni][0] = *(const uint32_t*)&Bs[cur][nc][kb + 2 * tg];
                bf[ni][1] = *(const uint32_t*)&Bs[cur][nc][kb + 2 * tg + 8];
            }
#pragma unroll
            for (int mi = 0; mi < 2; mi++)
#pragma unroll
                for (int ni = 0; ni < 8; ni++)
                    mma16816(acc[mi][ni], af[mi], bf[ni]);
        }
        if (it + 1 < nit) {
#pragma unroll
            for (int p = 0; p < 2; p++) {
                *(uint4*)&As[1 - cur][lr0 + p * 64][seg * 8] = sa[p];
                *(uint4*)&Bs[1 - cur][lr0 + p * 64][seg * 8] = sb[p];
            }
            __syncthreads();
        }
    }

    // epilogue: split cols <448 -> Cl, >=448 -> Cr
#pragma unroll
    for (int mi = 0; mi < 2; mi++) {
#pragma unroll
        for (int ni = 0; ni < 8; ni++) {
            int row = m0 + wm * 32 + mi * 16 + g;
            int cg = n0 + wn * 64 + ni * 8 + 2 * tg;
            float* base = (cg < HC) ? Cl : Cr;
            int cc = (cg < HC) ? cg : cg - HC;
            if (row < NN)
                *(float2*)&base[(size_t)row * HC + cc] =
                    make_float2(acc[mi][ni][0], acc[mi][ni][1]);
            if (row + 8 < NN)
                *(float2*)&base[(size_t)(row + 8) * HC + cc] =
                    make_float2(acc[mi][ni][2], acc[mi][ni][3]);
        }
    }
}

// ---------------- fused GATv2 edge kernel: barrier-free, shuffle reductions ----------------
__global__ __launch_bounds__(128) void k_gat(const float* __restrict__ xl,
                                             const float* __restrict__ xr,
                                             const float* __restrict__ We,
                                             const float* __restrict__ att,
                                             const float* __restrict__ bias,
                                             const float* __restrict__ eattr,
                                             const int* __restrict__ ei,
                                             float* __restrict__ out,
                                             int apply_elu) {
    __shared__ int s_eid[1024];
    __shared__ int s_srt[1024];
    int dst = blockIdx.x;
    int t = threadIdx.x;
    int start = g_cs[dst];
    int deg = g_cs[dst + 1] - start;
    for (int i = t; i < deg; i += 128) s_eid[i] = g_eid[start + i];
    __syncthreads();
    for (int i = t; i < deg; i += 128) {
        int key = s_eid[i]; int r = 0;
        for (int j = 0; j < deg; j++) r += (s_eid[j] < key);
        s_srt[r] = key;
    }
    __syncthreads();

    int g = t >> 4, l = t & 15;
    bool act = (l < 14);
    int c0 = g * 56 + l * 4;
    float4 xr4 = make_float4(0, 0, 0, 0), att4 = make_float4(0, 0, 0, 0);
    float4 We4[DE];
    float4 acc = make_float4(0, 0, 0, 0);
    float wsum = 0.f;
    if (act) {
        xr4 = *(const float4*)&xr[(size_t)dst * HC + c0];
        att4 = *(const float4*)&att[c0];
#pragma unroll
        for (int d = 0; d < DE; d++) We4[d] = *(const float4*)&We[d * HC + c0];
    }

    for (int i = 0; i < deg; i++) {
        int e = s_srt[i];
        float partial = 0.f;
        float4 xl4 = make_float4(0, 0, 0, 0);
        if (act) {
            int s; const float* ea;
            if (e < NE) { s = ei[e]; ea = eattr + (size_t)e * DE; }
            else        { s = dst;   ea = g_loop + (size_t)dst * DE; }
            xl4 = *(const float4*)&xl[(size_t)s * HC + c0];
            float e0 = ea[0], e1 = ea[1], e2 = ea[2], e3 = ea[3], e4 = ea[4];
            float sx = xl4.x + xr4.x + e0*We4[0].x + e1*We4[1].x + e2*We4[2].x + e3*We4[3].x + e4*We4[4].x;
            float sy = xl4.y + xr4.y + e0*We4[0].y + e1*We4[1].y + e2*We4[2].y + e3*We4[3].y + e4*We4[4].y;
            float sz = xl4.z + xr4.z + e0*We4[0].z + e1*We4[1].z + e2*We4[2].z + e3*We4[3].z + e4*We4[4].z;
            float sw = xl4.w + xr4.w + e0*We4[0].w + e1*We4[1].w + e2*We4[2].w + e3*We4[3].w + e4*We4[4].w;
            sx = (sx > 0.f) ? sx : NEG_SLOPE * sx;
            sy = (sy > 0.f) ? sy : NEG_SLOPE * sy;
            sz = (sz > 0.f) ? sz : NEG_SLOPE * sz;
            sw = (sw > 0.f) ? sw : NEG_SLOPE * sw;
            partial = att4.x*sx + att4.y*sy + att4.z*sz + att4.w*sw;
        }
        partial += __shfl_xor_sync(0xffffffffu, partial, 8);
        partial += __shfl_xor_sync(0xffffffffu, partial, 4);
        partial += __shfl_xor_sync(0xffffffffu, partial, 2);
        partial += __shfl_xor_sync(0xffffffffu, partial, 1);
        float w = expf(partial);
        if (act) {
            wsum += w;
            acc.x += w * xl4.x; acc.y += w * xl4.y;
            acc.z += w * xl4.z; acc.w += w * xl4.w;
        }
    }
    if (act) {
        float inv = 1.f / (wsum + 1e-16f);
        float4 b4 = *(const float4*)&bias[c0];
        float4 o;
        o.x = acc.x * inv + b4.x; o.y = acc.y * inv + b4.y;
        o.z = acc.z * inv + b4.z; o.w = acc.w * inv + b4.w;
        if (apply_elu) {
            o.x = (o.x > 0.f) ? o.x : expm1f(o.x);
            o.y = (o.y > 0.f) ? o.y : expm1f(o.y);
            o.z = (o.z > 0.f) ? o.z : expm1f(o.z);
            o.w = (o.w > 0.f) ? o.w : expm1f(o.w);
        }
        *(float4*)&out[(size_t)dst * HC + c0] = o;
    }
}

// ---------------- BatchNorm stats + coefficients ----------------
__global__ void k_bn_stats(const float* __restrict__ h) {
    int t = threadIdx.x;
    int r0 = blockIdx.x * 64;
    int rend = min(r0 + 64, NN);
    float s = 0.f, q = 0.f;
    for (int r = r0; r < rend; r++) {
        float v = h[(size_t)r * HC + t];
        s += v; q += v * v;
    }
    atomicAdd(&g_colsum[t], s);
    atomicAdd(&g_colsq[t], q);
}

__global__ void k_bn_coef(const float* __restrict__ gamma, const float* __restrict__ beta) {
    int t = threadIdx.x;
    if (t >= HC) return;
    float m = g_colsum[t] * (1.f / NN);
    float var = g_colsq[t] * (1.f / NN) - m * m;
    float sc = rsqrtf(var + EPS_BN) * gamma[t];
    g_scale[t] = sc;
    g_shift[t] = beta[t] - m * sc;
}

// ---------------- pooling ----------------
__global__ void k_gcount(const int* __restrict__ batch) {
    int i = blockIdx.x * blockDim.x + threadIdx.x;
    if (i < NN) atomicAdd(&g_gcnt[batch[i]], 1.f);
}

__global__ void k_pool_partial(const int* __restrict__ batch,
                               const float* __restrict__ h2) {
    int t = threadIdx.x;
    int r0 = blockIdx.x * 64;
    int rend = min(r0 + 64, NN);
    int g = -1; float acc = 0.f;
    for (int r = r0; r < rend; r++) {
        int bg = batch[r];
        if (bg != g) {
            if (g >= 0) atomicAdd(&g_pooled[g * HC + t], acc);
            g = bg; acc = 0.f;
        }
        acc += h2[(size_t)r * HC + t];
    }
    if (g >= 0) atomicAdd(&g_pooled[g * HC + t], acc);
}

// ---------------- final: mean, BN over 32 rows, linear(448->18), log_softmax ----------------
__global__ __launch_bounds__(512) void k_final(const float* __restrict__ gamma,
                                               const float* __restrict__ beta,
                                               const float* __restrict__ Wlin,
                                               const float* __restrict__ blin,
                                               float* __restrict__ out) {
    __shared__ float s_scale[HC];
    __shared__ float s_shift[HC];
    __shared__ float s_log[NG * 18];
    int t = threadIdx.x;
    for (int idx = t; idx < NG * HC; idx += 512) {
        int g = idx / HC;
        float c = fmaxf(g_gcnt[g], 1.f);
        g_pooled[idx] = g_pooled[idx] / c;
    }
    __syncthreads();
    if (t < HC) {
        float s = 0.f, q = 0.f;
        for (int g = 0; g < NG; g++) {
            float v = g_pooled[g * HC + t];
            s += v; q += v * v;
        }
        float m = s * (1.f / NG);
        float var = q * (1.f / NG) - m * m;
        float sc = rsqrtf(var + EPS_BN) * gamma[t];
        s_scale[t] = sc;
        s_shift[t] = beta[t] - m * sc;
    }
    __syncthreads();
    for (int o = t; o < NG * 18; o += 512) {
        int g = o / 18, j = o % 18;
        float acc = blin[j];
        for (int c = 0; c < HC; c++)
            acc += (g_pooled[g * HC + c] * s_scale[c] + s_shift[c]) * Wlin[c * 18 + j];
        s_log[o] = acc;
    }
    __syncthreads();
    if (t < NG) {
        float m = -1e30f;
        for (int j = 0; j < 18; j++) m = fmaxf(m, s_log[t * 18 + j]);
        float s = 0.f;
        for (int j = 0; j < 18; j++) s += expf(s_log[t * 18 + j] - m);
        float lse = m + logf(s);
        for (int j = 0; j < 18; j++) out[t * 18 + j] = s_log[t * 18 + j] - lse;
    }
}

// ---------------- host launcher ----------------
extern "C" void kernel_launch(void* const* d_in, const int* in_sizes, int n_in,
                              void* d_out, int out_size) {
    const float* x     = (const float*)d_in[0];
    const int*   ei    = (const int*)d_in[1];
    const float* eattr = (const float*)d_in[2];
    const int*   batch = (const int*)d_in[3];
    const float* Wl1   = (const float*)d_in[4];
    const float* Wr1   = (const float*)d_in[5];
    const float* We1   = (const float*)d_in[6];
    const float* att1  = (const float*)d_in[7];
    const float* bias1 = (const float*)d_in[8];
    const float* Wl2   = (const float*)d_in[9];
    const float* Wr2   = (const float*)d_in[10];
    const float* We2   = (const float*)d_in[11];
    const float* att2  = (const float*)d_in[12];
    const float* bias2 = (const float*)d_in[13];
    const float* gamma = (const float*)d_in[14];
    const float* beta  = (const float*)d_in[15];
    const float* Wlin  = (const float*)d_in[16];
    const float* blin  = (const float*)d_in[17];
    float* out = (float*)d_out;

    float *p_xl, *p_xr, *p_h, *p_h2;
    __half *p_a, *p_w;
    cudaGetSymbolAddress((void**)&p_xl, g_xl);
    cudaGetSymbolAddress((void**)&p_xr, g_xr);
    cudaGetSymbolAddress((void**)&p_h,  g_h);
    cudaGetSymbolAddress((void**)&p_h2, g_h2);
    cudaGetSymbolAddress((void**)&p_a,  g_af16);
    cudaGetSymbolAddress((void**)&p_w,  g_wt16);

    // graph prep
    k_zero<<<256, 256>>>();
    k_deg<<<(NE + 255) / 256, 256>>>(ei);
    k_scan1<<<NBLK, SB>>>();
    k_scan2<<<1, 128>>>();
    k_scan3<<<NBLK, SB>>>();
    k_scatter<<<(NE2 + 255) / 256, 256>>>(ei);
    k_loopattr_csr<<<(NN + 7) / 8, 256>>>(eattr);

    dim3 ggrid(2 * HC / BN, (NN + BM - 1) / BM);   // 7 x 157
    // layer 1
    k_prep_w<<<(2 * HC * DIN + 255) / 256, 256>>>(Wl1, Wr1, DIN);
    k_prep_a1<<<(NN * DIN + 255) / 256, 256>>>(x);
    gemm_f16<<<ggrid, 256>>>(DIN, p_a, p_w, p_xl, p_xr);
    k_gat<<<NN, 128>>>(p_xl, p_xr, We1, att1, bias1, eattr, ei, p_h, 1);
    // batchnorm coefs + layer-2 A prep (BN fused)
    k_bn_stats<<<(NN + 63) / 64, HC>>>(p_h);
    k_bn_coef<<<1, HC>>>(gamma, beta);
    k_prep_a2<<<(NN * HC + 255) / 256, 256>>>();
    // layer 2
    k_prep_w<<<(2 * HC * HC + 255) / 256, 256>>>(Wl2, Wr2, HC);
    gemm_f16<<<ggrid, 256>>>(HC, p_a, p_w, p_xl, p_xr);
    k_gat<<<NN, 128>>>(p_xl, p_xr, We2, att2, bias2, eattr, ei, p_h2, 0);
    // pool + head
    k_gcount<<<(NN + 255) / 256, 256>>>(batch);
    k_pool_partial<<<(NN + 63) / 64, HC>>>(batch, p_h2);
    k_final<<<1, 512>>>(gamma, beta, Wlin, blin, out);
}

// round 11
// speedup vs baseline: 1.9206x; 1.0663x over previous
#include <cuda_runtime.h>
#include <cuda_fp16.h>
#include <cstdint>
#include <cstddef>
#include <math.h>

#define NN   20000
#define NE   320000
#define NE2  340000
#define NG   32
#define NH   8
#define HC   448
#define DIN  32
#define DE   5
#define NEG_SLOPE 0.2f
#define EPS_BN 1e-5f

// ---------------- scratch (static device arrays: no allocation) ----------------
__device__ float g_xl[NN * HC];
__device__ float g_xr[NN * HC];
__device__ float g_h [NN * HC];
__device__ float g_h2[NN * HC];
__device__ float g_loop[NN * DE];
__device__ int   g_deg[NN];
__device__ int   g_cs[NN + 1];
__device__ int   g_cur[NN];
__device__ int   g_eid[NE2];
__device__ float g_colsum[HC];
__device__ float g_colsq[HC];
__device__ float g_pooled[NG * HC];
__device__ float g_gcnt[NG];
__device__ float g_scale[HC];
__device__ float g_shift[HC];
__device__ int   g_bsum[128];
__device__ int   g_boff[128];
__device__ __half g_af16[NN * HC];        // A in fp16, [NN][K]
__device__ __half g_wt16[2 * HC * HC];    // W^T in fp16, [896][K]

// ---------------- zero accumulators ----------------
__global__ void k_zero() {
    int i = blockIdx.x * blockDim.x + threadIdx.x;
    int st = gridDim.x * blockDim.x;
    for (int j = i; j < NN; j += st) g_deg[j] = 0;
    for (int j = i; j < HC; j += st) { g_colsum[j] = 0.f; g_colsq[j] = 0.f; }
    for (int j = i; j < NG * HC; j += st) g_pooled[j] = 0.f;
    for (int j = i; j < NG; j += st) g_gcnt[j] = 0.f;
}

// ---------------- degree ----------------
__global__ void k_deg(const int* __restrict__ ei) {
    int e = blockIdx.x * blockDim.x + threadIdx.x;
    if (e < NE) atomicAdd(&g_deg[ei[NE + e]], 1);
}

// ---------------- 3-kernel parallel exclusive scan of (deg+1) ----------------
#define SB 256
#define NBLK 79
__global__ void k_scan1() {
    int b = blockIdx.x, t = threadIdx.x;
    int idx = b * SB + t;
    int v = (idx < NN) ? g_deg[idx] + 1 : 0;
    int s = v;
#pragma unroll
    for (int o = 16; o >= 1; o >>= 1) s += __shfl_xor_sync(0xffffffffu, s, o);
    __shared__ int ws[8];
    if ((t & 31) == 0) ws[t >> 5] = s;
    __syncthreads();
    if (t == 0) {
        int tot = 0;
#pragma unroll
        for (int w = 0; w < 8; w++) tot += ws[w];
        g_bsum[b] = tot;
    }
}
__global__ void k_scan2() {
    __shared__ int sv[128];
    int t = threadIdx.x;
    int v = (t < NBLK) ? g_bsum[t] : 0;
    sv[t] = v;
    __syncthreads();
    for (int off = 1; off < 128; off <<= 1) {
        int u = (t >= off) ? sv[t - off] : 0;
        __syncthreads();
        sv[t] += u;
        __syncthreads();
    }
    if (t < NBLK) g_boff[t] = sv[t] - v;   // exclusive
    if (t == NBLK - 1) g_cs[NN] = sv[t];   // total
}
__global__ void k_scan3() {
    int b = blockIdx.x, t = threadIdx.x;
    int lane = t & 31, wid = t >> 5;
    int idx = b * SB + t;
    int v = (idx < NN) ? g_deg[idx] + 1 : 0;
    int inc = v;
#pragma unroll
    for (int o = 1; o < 32; o <<= 1) {
        int u = __shfl_up_sync(0xffffffffu, inc, o);
        if (lane >= o) inc += u;
    }
    __shared__ int ws[8];
    if (lane == 31) ws[wid] = inc;
    __syncthreads();
    if (wid == 0 && lane < 8) {
        int wv = ws[lane];
#pragma unroll
        for (int o = 1; o < 8; o <<= 1) {
            int u = __shfl_up_sync(0xffu, wv, o);
            if (lane >= o) wv += u;
        }
        ws[lane] = wv;
    }
    __syncthreads();
    int base = g_boff[b] + (wid > 0 ? ws[wid - 1] : 0);
    int ex = base + inc - v;
    if (idx < NN) { g_cs[idx] = ex; g_cur[idx] = ex; }
}

// ---------------- scatter edge ids into CSR buckets ----------------
__global__ void k_scatter(const int* __restrict__ ei) {
    int e = blockIdx.x * blockDim.x + threadIdx.x;
    if (e >= NE2) return;
    int d = (e < NE) ? ei[NE + e] : (e - NE);
    int pos = atomicAdd(&g_cur[d], 1);
    g_eid[pos] = e;
}

// ---------------- self-loop attr via CSR: one warp per node ----------------
__global__ void k_loopattr_csr(const float* __restrict__ eattr) {
    int w = blockIdx.x * 8 + (threadIdx.x >> 5);
    int lane = threadIdx.x & 31;
    if (w >= NN) return;
    int s0 = g_cs[w];
    int n = g_cs[w + 1] - s0;
    float a0 = 0.f, a1 = 0.f, a2 = 0.f, a3 = 0.f, a4 = 0.f;
    for (int i = lane; i < n; i += 32) {
        int e = g_eid[s0 + i];
        if (e < NE) {
            const float* p = eattr + (size_t)e * DE;
            a0 += p[0]; a1 += p[1]; a2 += p[2]; a3 += p[3]; a4 += p[4];
        }
    }
#pragma unroll
    for (int o = 16; o >= 1; o >>= 1) {
        a0 += __shfl_xor_sync(0xffffffffu, a0, o);
        a1 += __shfl_xor_sync(0xffffffffu, a1, o);
        a2 += __shfl_xor_sync(0xffffffffu, a2, o);
        a3 += __shfl_xor_sync(0xffffffffu, a3, o);
        a4 += __shfl_xor_sync(0xffffffffu, a4, o);
    }
    if (lane == 0) {
        float dg = fmaxf((float)g_deg[w], 1.f);
        g_loop[w * DE + 0] = a0 / dg;
        g_loop[w * DE + 1] = a1 / dg;
        g_loop[w * DE + 2] = a2 / dg;
        g_loop[w * DE + 3] = a3 / dg;
        g_loop[w * DE + 4] = a4 / dg;
    }
}

// ---------------- weight prep: W^T -> fp16, [896][K] ----------------
__global__ void k_prep_w(const float* __restrict__ Wl, const float* __restrict__ Wr, int K) {
    int i = blockIdx.x * blockDim.x + threadIdx.x;
    if (i >= 2 * HC * K) return;
    int n = i / K, k = i % K;
    float v = (n < HC) ? Wl[k * HC + n] : Wr[k * HC + (n - HC)];
    g_wt16[i] = __float2half(v);
}

// ---------------- A prep layer1: x -> fp16, [NN][32] ----------------
__global__ void k_prep_a1(const float* __restrict__ x) {
    int i = blockIdx.x * blockDim.x + threadIdx.x;
    if (i < NN * DIN) g_af16[i] = __float2half(x[i]);
}

// ---------------- A prep layer2: BN(h) fused -> fp16 ----------------
__global__ void k_prep_a2() {
    int i = blockIdx.x * blockDim.x + threadIdx.x;
    if (i >= NN * HC) return;
    int c = i % HC;
    g_af16[i] = __float2half(g_h[i] * g_scale[c] + g_shift[c]);
}

// ======================= fp16 mma.sync GEMM (ldmatrix fragments) ===============
// C[NN, 896] = A[NN, K] @ W[K, 896]; W^T given as [896][K] fp16.
// BM=128, BN=128, BK=32; 256 threads = 8 warps (4 x 2), warp tile 32x64.
#define BM 128
#define BN 128
#define BK 32
#define APITCH 40   // halves: conflict-free (banks (20r+t) mod 32 distinct)

__device__ __forceinline__ void mma16816(float* c, const uint32_t* a, const uint32_t* b) {
    asm volatile(
        "mma.sync.aligned.m16n8k16.row.col.f32.f16.f16.f32 "
        "{%0,%1,%2,%3}, {%4,%5,%6,%7}, {%8,%9}, {%0,%1,%2,%3};\n"
        : "+f"(c[0]), "+f"(c[1]), "+f"(c[2]), "+f"(c[3])
        : "r"(a[0]), "r"(a[1]), "r"(a[2]), "r"(a[3]), "r"(b[0]), "r"(b[1]));
}

__device__ __forceinline__ void ldsm4(uint32_t* r, uint32_t addr) {
    asm volatile("ldmatrix.sync.aligned.m8n8.x4.shared.b16 {%0,%1,%2,%3}, [%4];"
        : "=r"(r[0]), "=r"(r[1]), "=r"(r[2]), "=r"(r[3]) : "r"(addr));
}

__global__ __launch_bounds__(256) void gemm_f16(int K,
                                                const __half* __restrict__ A,
                                                const __half* __restrict__ W,
                                                float* __restrict__ Cl,
                                                float* __restrict__ Cr) {
    __shared__ __half As[2][BM][APITCH];
    __shared__ __half Bs[2][BN][APITCH];
    const int tid = threadIdx.x, lane = tid & 31, wid = tid >> 5;
    const int wm = wid & 3, wn = wid >> 2;       // 4 x 2 warp grid
    const int g = lane >> 2, tg = lane & 3;
    const int m0 = blockIdx.y * BM, n0 = blockIdx.x * BN;
    const int nit = K / BK;

    float acc[2][8][4];
#pragma unroll
    for (int mi = 0; mi < 2; mi++)
#pragma unroll
        for (int ni = 0; ni < 8; ni++)
#pragma unroll
            for (int r = 0; r < 4; r++) acc[mi][ni][r] = 0.f;

    // ldmatrix per-lane invariant byte offsets
    const uint32_t asb = (uint32_t)__cvta_generic_to_shared(&As[0][0][0]);
    const uint32_t bsb = (uint32_t)__cvta_generic_to_shared(&Bs[0][0][0]);
    const uint32_t a_lo = ((uint32_t)(wm * 32 + (lane & 15)) * APITCH + (lane >> 4) * 8) * 2;
    const uint32_t b_lo = ((uint32_t)(wn * 64 + (lane & 7) + ((lane >> 4) & 1) * 8) * APITCH
                          + ((lane >> 3) & 1) * 8) * 2;

    // load mapping: 128 rows x 4 segs of 16B; two groups per thread
    const int lr0 = tid >> 2, seg = tid & 3;     // rows lr0 and lr0+64

    uint4 sa[2], sb[2];
    // prologue: kc0 = 0
    {
#pragma unroll
        for (int p = 0; p < 2; p++) {
            int r = m0 + lr0 + p * 64;
            sa[p] = make_uint4(0u, 0u, 0u, 0u);
            if (r < NN) sa[p] = *(const uint4*)(A + (size_t)r * K + seg * 8);
            sb[p] = *(const uint4*)(W + (size_t)(n0 + lr0 + p * 64) * K + seg * 8);
        }
#pragma unroll
        for (int p = 0; p < 2; p++) {
            *(uint4*)&As[0][lr0 + p * 64][seg * 8] = sa[p];
            *(uint4*)&Bs[0][lr0 + p * 64][seg * 8] = sb[p];
        }
    }
    __syncthreads();

    for (int it = 0; it < nit; ++it) {
        int cur = it & 1;
        if (it + 1 < nit) {
            int kc0 = (it + 1) * BK;
#pragma unroll
            for (int p = 0; p < 2; p++) {
                int r = m0 + lr0 + p * 64;
                sa[p] = make_uint4(0u, 0u, 0u, 0u);
                if (r < NN) sa[p] = *(const uint4*)(A + (size_t)r * K + kc0 + seg * 8);
                sb[p] = *(const uint4*)(W + (size_t)(n0 + lr0 + p * 64) * K + kc0 + seg * 8);
            }
        }
        uint32_t abase = asb + (uint32_t)cur * (BM * APITCH * 2) + a_lo;
        uint32_t bbase = bsb + (uint32_t)cur * (BN * APITCH * 2) + b_lo;
#pragma unroll
        for (int ks = 0; ks < 2; ks++) {
            uint32_t koff = (uint32_t)(ks * 16) * 2;
            uint32_t af[2][4], bf[8][2];
#pragma unroll
            for (int mi = 0; mi < 2; mi++)
                ldsm4(af[mi], abase + (uint32_t)(mi * 16 * APITCH * 2) + koff);
#pragma unroll
            for (int p = 0; p < 4; p++) {
                uint32_t tmp[4];
                ldsm4(tmp, bbase + (uint32_t)(p * 16 * APITCH * 2) + koff);
                bf[2 * p][0] = tmp[0]; bf[2 * p][1] = tmp[1];
                bf[2 * p + 1][0] = tmp[2]; bf[2 * p + 1][1] = tmp[3];
            }
#pragma unroll
            for (int mi = 0; mi < 2; mi++)
#pragma unroll
                for (int ni = 0; ni < 8; ni++)
                    mma16816(acc[mi][ni], af[mi], bf[ni]);
        }
        if (it + 1 < nit) {
#pragma unroll
            for (int p = 0; p < 2; p++) {
                *(uint4*)&As[1 - cur][lr0 + p * 64][seg * 8] = sa[p];
                *(uint4*)&Bs[1 - cur][lr0 + p * 64][seg * 8] = sb[p];
            }
            __syncthreads();
        }
    }

    // epilogue: split cols <448 -> Cl, >=448 -> Cr
#pragma unroll
    for (int mi = 0; mi < 2; mi++) {
#pragma unroll
        for (int ni = 0; ni < 8; ni++) {
            int row = m0 + wm * 32 + mi * 16 + g;
            int cg = n0 + wn * 64 + ni * 8 + 2 * tg;
            float* base = (cg < HC) ? Cl : Cr;
            int cc = (cg < HC) ? cg : cg - HC;
            if (row < NN)
                *(float2*)&base[(size_t)row * HC + cc] =
                    make_float2(acc[mi][ni][0], acc[mi][ni][1]);
            if (row + 8 < NN)
                *(float2*)&base[(size_t)(row + 8) * HC + cc] =
                    make_float2(acc[mi][ni][2], acc[mi][ni][3]);
        }
    }
}

// ---------------- fused GATv2 edge kernel: prefetch-pipelined, shuffle reductions --
__global__ __launch_bounds__(128) void k_gat(const float* __restrict__ xl,
                                             const float* __restrict__ xr,
                                             const float* __restrict__ We,
                                             const float* __restrict__ att,
                                             const float* __restrict__ bias,
                                             const float* __restrict__ eattr,
                                             const int* __restrict__ ei,
                                             float* __restrict__ out,
                                             int apply_elu) {
    __shared__ int s_eid[1024];
    __shared__ int s_srt[1024];
    int dst = blockIdx.x;
    int t = threadIdx.x;
    int start = g_cs[dst];
    int deg = g_cs[dst + 1] - start;
    for (int i = t; i < deg; i += 128) s_eid[i] = g_eid[start + i];
    __syncthreads();
    for (int i = t; i < deg; i += 128) {
        int key = s_eid[i]; int r = 0;
        for (int j = 0; j < deg; j++) r += (s_eid[j] < key);
        s_srt[r] = key;
    }
    __syncthreads();

    int g = t >> 4, l = t & 15;
    bool act = (l < 14);
    int c0 = g * 56 + l * 4;
    float4 xr4 = make_float4(0, 0, 0, 0), att4 = make_float4(0, 0, 0, 0);
    float4 We4[DE];
    float4 acc = make_float4(0, 0, 0, 0);
    float wsum = 0.f;
    if (act) {
        xr4 = *(const float4*)&xr[(size_t)dst * HC + c0];
        att4 = *(const float4*)&att[c0];
#pragma unroll
        for (int d = 0; d < DE; d++) We4[d] = *(const float4*)&We[d * HC + c0];
    }

    float4 xl_nxt = make_float4(0, 0, 0, 0);
    float ea_nxt[DE] = {0.f, 0.f, 0.f, 0.f, 0.f};
    if (act && deg > 0) {
        int e = s_srt[0];
        int s; const float* ea;
        if (e < NE) { s = ei[e]; ea = eattr + (size_t)e * DE; }
        else        { s = dst;   ea = g_loop + (size_t)dst * DE; }
        xl_nxt = *(const float4*)&xl[(size_t)s * HC + c0];
#pragma unroll
        for (int d = 0; d < DE; d++) ea_nxt[d] = ea[d];
    }

    for (int i = 0; i < deg; i++) {
        float4 xl4 = xl_nxt;
        float e0 = ea_nxt[0], e1 = ea_nxt[1], e2 = ea_nxt[2], e3 = ea_nxt[3], e4 = ea_nxt[4];
        if (act && i + 1 < deg) {          // prefetch next edge before the shfl chain
            int e = s_srt[i + 1];
            int s; const float* ea;
            if (e < NE) { s = ei[e]; ea = eattr + (size_t)e * DE; }
            else        { s = dst;   ea = g_loop + (size_t)dst * DE; }
            xl_nxt = *(const float4*)&xl[(size_t)s * HC + c0];
#pragma unroll
            for (int d = 0; d < DE; d++) ea_nxt[d] = ea[d];
        }
        float partial = 0.f;
        if (act) {
            float sx = xl4.x + xr4.x + e0*We4[0].x + e1*We4[1].x + e2*We4[2].x + e3*We4[3].x + e4*We4[4].x;
            float sy = xl4.y + xr4.y + e0*We4[0].y + e1*We4[1].y + e2*We4[2].y + e3*We4[3].y + e4*We4[4].y;
            float sz = xl4.z + xr4.z + e0*We4[0].z + e1*We4[1].z + e2*We4[2].z + e3*We4[3].z + e4*We4[4].z;
            float sw = xl4.w + xr4.w + e0*We4[0].w + e1*We4[1].w + e2*We4[2].w + e3*We4[3].w + e4*We4[4].w;
            sx = (sx > 0.f) ? sx : NEG_SLOPE * sx;
            sy = (sy > 0.f) ? sy : NEG_SLOPE * sy;
            sz = (sz > 0.f) ? sz : NEG_SLOPE * sz;
            sw = (sw > 0.f) ? sw : NEG_SLOPE * sw;
            partial = att4.x*sx + att4.y*sy + att4.z*sz + att4.w*sw;
        }
        partial += __shfl_xor_sync(0xffffffffu, partial, 8);
        partial += __shfl_xor_sync(0xffffffffu, partial, 4);
        partial += __shfl_xor_sync(0xffffffffu, partial, 2);
        partial += __shfl_xor_sync(0xffffffffu, partial, 1);
        float w = expf(partial);
        if (act) {
            wsum += w;
            acc.x += w * xl4.x; acc.y += w * xl4.y;
            acc.z += w * xl4.z; acc.w += w * xl4.w;
        }
    }
    if (act) {
        float inv = 1.f / (wsum + 1e-16f);
        float4 b4 = *(const float4*)&bias[c0];
        float4 o;
        o.x = acc.x * inv + b4.x; o.y = acc.y * inv + b4.y;
        o.z = acc.z * inv + b4.z; o.w = acc.w * inv + b4.w;
        if (apply_elu) {
            o.x = (o.x > 0.f) ? o.x : expm1f(o.x);
            o.y = (o.y > 0.f) ? o.y : expm1f(o.y);
            o.z = (o.z > 0.f) ? o.z : expm1f(o.z);
            o.w = (o.w > 0.f) ? o.w : expm1f(o.w);
        }
        *(float4*)&out[(size_t)dst * HC + c0] = o;
    }
}

// ---------------- BatchNorm stats + coefficients ----------------
__global__ void k_bn_stats(const float* __restrict__ h) {
    int t = threadIdx.x;
    int r0 = blockIdx.x * 64;
    int rend = min(r0 + 64, NN);
    float s = 0.f, q = 0.f;
    for (int r = r0; r < rend; r++) {
        float v = h[(size_t)r * HC + t];
        s += v; q += v * v;
    }
    atomicAdd(&g_colsum[t], s);
    atomicAdd(&g_colsq[t], q);
}

__global__ void k_bn_coef(const float* __restrict__ gamma, const float* __restrict__ beta) {
    int t = threadIdx.x;
    if (t >= HC) return;
    float m = g_colsum[t] * (1.f / NN);
    float var = g_colsq[t] * (1.f / NN) - m * m;
    float sc = rsqrtf(var + EPS_BN) * gamma[t];
    g_scale[t] = sc;
    g_shift[t] = beta[t] - m * sc;
}

// ---------------- pooling ----------------
__global__ void k_gcount(const int* __restrict__ batch) {
    int i = blockIdx.x * blockDim.x + threadIdx.x;
    if (i < NN) atomicAdd(&g_gcnt[batch[i]], 1.f);
}

__global__ void k_pool_partial(const int* __restrict__ batch,
                               const float* __restrict__ h2) {
    int t = threadIdx.x;
    int r0 = blockIdx.x * 64;
    int rend = min(r0 + 64, NN);
    int g = -1; float acc = 0.f;
    for (int r = r0; r < rend; r++) {
        int bg = batch[r];
        if (bg != g) {
            if (g >= 0) atomicAdd(&g_pooled[g * HC + t], acc);
            g = bg; acc = 0.f;
        }
        acc += h2[(size_t)r * HC + t];
    }
    if (g >= 0) atomicAdd(&g_pooled[g * HC + t], acc);
}

// ---------------- final: mean, BN over 32 rows, linear(448->18), log_softmax ------
__global__ __launch_bounds__(512) void k_final(const float* __restrict__ gamma,
                                               const float* __restrict__ beta,
                                               const float* __restrict__ Wlin,
                                               const float* __restrict__ blin,
                                               float* __restrict__ out) {
    __shared__ float s_scale[HC];
    __shared__ float s_shift[HC];
    __shared__ float s_log[NG * 18];
    int t = threadIdx.x;
    for (int idx = t; idx < NG * HC; idx += 512) {
        int g = idx / HC;
        float c = fmaxf(g_gcnt[g], 1.f);
        g_pooled[idx] = g_pooled[idx] / c;
    }
    __syncthreads();
    if (t < HC) {
        float s = 0.f, q = 0.f;
        for (int g = 0; g < NG; g++) {
            float v = g_pooled[g * HC + t];
            s += v; q += v * v;
        }
        float m = s * (1.f / NG);
        float var = q * (1.f / NG) - m * m;
        float sc = rsqrtf(var + EPS_BN) * gamma[t];
        s_scale[t] = sc;
        s_shift[t] = beta[t] - m * sc;
    }
    __syncthreads();
    for (int o = t; o < NG * 18; o += 512) {
        int g = o / 18, j = o % 18;
        float acc = blin[j];
        for (int c = 0; c < HC; c++)
            acc += (g_pooled[g * HC + c] * s_scale[c] + s_shift[c]) * Wlin[c * 18 + j];
        s_log[o] = acc;
    }
    __syncthreads();
    if (t < NG) {
        float m = -1e30f;
        for (int j = 0; j < 18; j++) m = fmaxf(m, s_log[t * 18 + j]);
        float s = 0.f;
        for (int j = 0; j < 18; j++) s += expf(s_log[t * 18 + j] - m);
        float lse = m + logf(s);
        for (int j = 0; j < 18; j++) out[t * 18 + j] = s_log[t * 18 + j] - lse;
    }
}

// ---------------- host launcher ----------------
extern "C" void kernel_launch(void* const* d_in, const int* in_sizes, int n_in,
                              void* d_out, int out_size) {
    const float* x     = (const float*)d_in[0];
    const int*   ei    = (const int*)d_in[1];
    const float* eattr = (const float*)d_in[2];
    const int*   batch = (const int*)d_in[3];
    const float* Wl1   = (const float*)d_in[4];
    const float* Wr1   = (const float*)d_in[5];
    const float* We1   = (const float*)d_in[6];
    const float* att1  = (const float*)d_in[7];
    const float* bias1 = (const float*)d_in[8];
    const float* Wl2   = (const float*)d_in[9];
    const float* Wr2   = (const float*)d_in[10];
    const float* We2   = (const float*)d_in[11];
    const float* att2  = (const float*)d_in[12];
    const float* bias2 = (const float*)d_in[13];
    const float* gamma = (const float*)d_in[14];
    const float* beta  = (const float*)d_in[15];
    const float* Wlin  = (const float*)d_in[16];
    const float* blin  = (const float*)d_in[17];
    float* out = (float*)d_out;

    float *p_xl, *p_xr, *p_h, *p_h2;
    __half *p_a, *p_w;
    cudaGetSymbolAddress((void**)&p_xl, g_xl);
    cudaGetSymbolAddress((void**)&p_xr, g_xr);
    cudaGetSymbolAddress((void**)&p_h,  g_h);
    cudaGetSymbolAddress((void**)&p_h2, g_h2);
    cudaGetSymbolAddress((void**)&p_a,  g_af16);
    cudaGetSymbolAddress((void**)&p_w,  g_wt16);

    dim3 ggrid(2 * HC / BN, (NN + BM - 1) / BM);   // 7 x 157

    // layer-1 GEMM first (launch index 3 = ncu capture slot)
    k_zero<<<256, 256>>>();
    k_prep_w<<<(2 * HC * DIN + 255) / 256, 256>>>(Wl1, Wr1, DIN);
    k_prep_a1<<<(NN * DIN + 255) / 256, 256>>>(x);
    gemm_f16<<<ggrid, 256>>>(DIN, p_a, p_w, p_xl, p_xr);

    // graph prep
    k_deg<<<(NE + 255) / 256, 256>>>(ei);
    k_scan1<<<NBLK, SB>>>();
    k_scan2<<<1, 128>>>();
    k_scan3<<<NBLK, SB>>>();
    k_scatter<<<(NE2 + 255) / 256, 256>>>(ei);
    k_loopattr_csr<<<(NN + 7) / 8, 256>>>(eattr);

    // layer 1 aggregate
    k_gat<<<NN, 128>>>(p_xl, p_xr, We1, att1, bias1, eattr, ei, p_h, 1);
    // batchnorm coefs + layer-2 A prep (BN fused)
    k_bn_stats<<<(NN + 63) / 64, HC>>>(p_h);
    k_bn_coef<<<1, HC>>>(gamma, beta);
    k_prep_a2<<<(NN * HC + 255) / 256, 256>>>();
    // layer 2
    k_prep_w<<<(2 * HC * HC + 255) / 256, 256>>>(Wl2, Wr2, HC);
    gemm_f16<<<ggrid, 256>>>(HC, p_a, p_w, p_xl, p_xr);
    k_gat<<<NN, 128>>>(p_xl, p_xr, We2, att2, bias2, eattr, ei, p_h2, 0);
    // pool + head
    k_gcount<<<(NN + 255) / 256, 256>>>(batch);
    k_pool_partial<<<(NN + 63) / 64, HC>>>(batch, p_h2);
    k_final<<<1, 512>>>(gamma, beta, Wlin, blin, out);
}

// round 12
// speedup vs baseline: 2.0013x; 1.0420x over previous
#include <cuda_runtime.h>
#include <cuda_fp16.h>
#include <cstdint>
#include <cstddef>
#include <math.h>

#define NN   20000
#define NE   320000
#define NE2  340000
#define NG   32
#define NH   8
#define HC   448
#define DIN  32
#define DE   5
#define NEG_SLOPE 0.2f
#define EPS_BN 1e-5f

// ---------------- scratch (static device arrays: no allocation) ----------------
__device__ __half g_xl[NN * HC];          // fp16 transformed features
__device__ __half g_xr[NN * HC];
__device__ float g_h [NN * HC];
__device__ float g_h2[NN * HC];
__device__ float g_loop[NN * DE];
__device__ int   g_deg[NN];
__device__ int   g_cs[NN + 1];
__device__ int   g_cur[NN];
__device__ int   g_eid[NE2];
__device__ float g_colsum[HC];
__device__ float g_colsq[HC];
__device__ float g_pooled[NG * HC];
__device__ float g_gcnt[NG];
__device__ float g_scale[HC];
__device__ float g_shift[HC];
__device__ int   g_bsum[128];
__device__ int   g_boff[128];
__device__ __half g_af16[NN * HC];        // A in fp16, [NN][K]
__device__ __half g_wt16[2 * HC * HC];    // W^T in fp16, [896][K]

// ---------------- zero accumulators ----------------
__global__ void k_zero() {
    int i = blockIdx.x * blockDim.x + threadIdx.x;
    int st = gridDim.x * blockDim.x;
    for (int j = i; j < NN; j += st) g_deg[j] = 0;
    for (int j = i; j < HC; j += st) { g_colsum[j] = 0.f; g_colsq[j] = 0.f; }
    for (int j = i; j < NG * HC; j += st) g_pooled[j] = 0.f;
    for (int j = i; j < NG; j += st) g_gcnt[j] = 0.f;
}

// ---------------- degree ----------------
__global__ void k_deg(const int* __restrict__ ei) {
    int e = blockIdx.x * blockDim.x + threadIdx.x;
    if (e < NE) atomicAdd(&g_deg[ei[NE + e]], 1);
}

// ---------------- 3-kernel parallel exclusive scan of (deg+1) ----------------
#define SB 256
#define NBLK 79
__global__ void k_scan1() {
    int b = blockIdx.x, t = threadIdx.x;
    int idx = b * SB + t;
    int v = (idx < NN) ? g_deg[idx] + 1 : 0;
    int s = v;
#pragma unroll
    for (int o = 16; o >= 1; o >>= 1) s += __shfl_xor_sync(0xffffffffu, s, o);
    __shared__ int ws[8];
    if ((t & 31) == 0) ws[t >> 5] = s;
    __syncthreads();
    if (t == 0) {
        int tot = 0;
#pragma unroll
        for (int w = 0; w < 8; w++) tot += ws[w];
        g_bsum[b] = tot;
    }
}
__global__ void k_scan2() {
    __shared__ int sv[128];
    int t = threadIdx.x;
    int v = (t < NBLK) ? g_bsum[t] : 0;
    sv[t] = v;
    __syncthreads();
    for (int off = 1; off < 128; off <<= 1) {
        int u = (t >= off) ? sv[t - off] : 0;
        __syncthreads();
        sv[t] += u;
        __syncthreads();
    }
    if (t < NBLK) g_boff[t] = sv[t] - v;   // exclusive
    if (t == NBLK - 1) g_cs[NN] = sv[t];   // total
}
__global__ void k_scan3() {
    int b = blockIdx.x, t = threadIdx.x;
    int lane = t & 31, wid = t >> 5;
    int idx = b * SB + t;
    int v = (idx < NN) ? g_deg[idx] + 1 : 0;
    int inc = v;
#pragma unroll
    for (int o = 1; o < 32; o <<= 1) {
        int u = __shfl_up_sync(0xffffffffu, inc, o);
        if (lane >= o) inc += u;
    }
    __shared__ int ws[8];
    if (lane == 31) ws[wid] = inc;
    __syncthreads();
    if (wid == 0 && lane < 8) {
        int wv = ws[lane];
#pragma unroll
        for (int o = 1; o < 8; o <<= 1) {
            int u = __shfl_up_sync(0xffu, wv, o);
            if (lane >= o) wv += u;
        }
        ws[lane] = wv;
    }
    __syncthreads();
    int base = g_boff[b] + (wid > 0 ? ws[wid - 1] : 0);
    int ex = base + inc - v;
    if (idx < NN) { g_cs[idx] = ex; g_cur[idx] = ex; }
}

// ---------------- scatter edge ids into CSR buckets ----------------
__global__ void k_scatter(const int* __restrict__ ei) {
    int e = blockIdx.x * blockDim.x + threadIdx.x;
    if (e >= NE2) return;
    int d = (e < NE) ? ei[NE + e] : (e - NE);
    int pos = atomicAdd(&g_cur[d], 1);
    g_eid[pos] = e;
}

// ---------------- self-loop attr via CSR: one warp per node ----------------
__global__ void k_loopattr_csr(const float* __restrict__ eattr) {
    int w = blockIdx.x * 8 + (threadIdx.x >> 5);
    int lane = threadIdx.x & 31;
    if (w >= NN) return;
    int s0 = g_cs[w];
    int n = g_cs[w + 1] - s0;
    float a0 = 0.f, a1 = 0.f, a2 = 0.f, a3 = 0.f, a4 = 0.f;
    for (int i = lane; i < n; i += 32) {
        int e = g_eid[s0 + i];
        if (e < NE) {
            const float* p = eattr + (size_t)e * DE;
            a0 += p[0]; a1 += p[1]; a2 += p[2]; a3 += p[3]; a4 += p[4];
        }
    }
#pragma unroll
    for (int o = 16; o >= 1; o >>= 1) {
        a0 += __shfl_xor_sync(0xffffffffu, a0, o);
        a1 += __shfl_xor_sync(0xffffffffu, a1, o);
        a2 += __shfl_xor_sync(0xffffffffu, a2, o);
        a3 += __shfl_xor_sync(0xffffffffu, a3, o);
        a4 += __shfl_xor_sync(0xffffffffu, a4, o);
    }
    if (lane == 0) {
        float dg = fmaxf((float)g_deg[w], 1.f);
        g_loop[w * DE + 0] = a0 / dg;
        g_loop[w * DE + 1] = a1 / dg;
        g_loop[w * DE + 2] = a2 / dg;
        g_loop[w * DE + 3] = a3 / dg;
        g_loop[w * DE + 4] = a4 / dg;
    }
}

// ---------------- weight prep: W^T -> fp16, [896][K] ----------------
__global__ void k_prep_w(const float* __restrict__ Wl, const float* __restrict__ Wr, int K) {
    int i = blockIdx.x * blockDim.x + threadIdx.x;
    if (i >= 2 * HC * K) return;
    int n = i / K, k = i % K;
    float v = (n < HC) ? Wl[k * HC + n] : Wr[k * HC + (n - HC)];
    g_wt16[i] = __float2half(v);
}

// ---------------- A prep layer1: x -> fp16, [NN][32] ----------------
__global__ void k_prep_a1(const float* __restrict__ x) {
    int i = blockIdx.x * blockDim.x + threadIdx.x;
    if (i < NN * DIN) g_af16[i] = __float2half(x[i]);
}

// ---------------- A prep layer2: BN(h) fused -> fp16 ----------------
__global__ void k_prep_a2() {
    int i = blockIdx.x * blockDim.x + threadIdx.x;
    if (i >= NN * HC) return;
    int c = i % HC;
    g_af16[i] = __float2half(g_h[i] * g_scale[c] + g_shift[c]);
}

// ======================= fp16 mma.sync GEMM (ldmatrix + cp.async) ==============
#define BM 128
#define BN 128
#define BK 32
#define APITCH 40

__device__ __forceinline__ void mma16816(float* c, const uint32_t* a, const uint32_t* b) {
    asm volatile(
        "mma.sync.aligned.m16n8k16.row.col.f32.f16.f16.f32 "
        "{%0,%1,%2,%3}, {%4,%5,%6,%7}, {%8,%9}, {%0,%1,%2,%3};\n"
        : "+f"(c[0]), "+f"(c[1]), "+f"(c[2]), "+f"(c[3])
        : "r"(a[0]), "r"(a[1]), "r"(a[2]), "r"(a[3]), "r"(b[0]), "r"(b[1]));
}
__device__ __forceinline__ void ldsm4(uint32_t* r, uint32_t addr) {
    asm volatile("ldmatrix.sync.aligned.m8n8.x4.shared.b16 {%0,%1,%2,%3}, [%4];"
        : "=r"(r[0]), "=r"(r[1]), "=r"(r[2]), "=r"(r[3]) : "r"(addr));
}
__device__ __forceinline__ void cp16(uint32_t dst, const void* src) {
    asm volatile("cp.async.cg.shared.global [%0], [%1], 16;" :: "r"(dst), "l"(src));
}
__device__ __forceinline__ void cp16z(uint32_t dst, const void* src) {
    asm volatile("cp.async.cg.shared.global [%0], [%1], 16, 0;" :: "r"(dst), "l"(src));
}
__device__ __forceinline__ void cp_commit() { asm volatile("cp.async.commit_group;"); }
__device__ __forceinline__ void cp_wait0()  { asm volatile("cp.async.wait_group 0;" ::: "memory"); }

__global__ __launch_bounds__(256) void gemm_f16(int K,
                                                const __half* __restrict__ A,
                                                const __half* __restrict__ W,
                                                __half* __restrict__ Cl,
                                                __half* __restrict__ Cr) {
    __shared__ __half As[2][BM][APITCH];
    __shared__ __half Bs[2][BN][APITCH];
    const int tid = threadIdx.x, lane = tid & 31, wid = tid >> 5;
    const int wm = wid & 3, wn = wid >> 2;
    const int g = lane >> 2, tg = lane & 3;
    const int m0 = blockIdx.y * BM, n0 = blockIdx.x * BN;
    const int nit = K / BK;

    float acc[2][8][4];
#pragma unroll
    for (int mi = 0; mi < 2; mi++)
#pragma unroll
        for (int ni = 0; ni < 8; ni++)
#pragma unroll
            for (int r = 0; r < 4; r++) acc[mi][ni][r] = 0.f;

    const uint32_t asb = (uint32_t)__cvta_generic_to_shared(&As[0][0][0]);
    const uint32_t bsb = (uint32_t)__cvta_generic_to_shared(&Bs[0][0][0]);
    const uint32_t a_lo = ((uint32_t)(wm * 32 + (lane & 15)) * APITCH + (lane >> 4) * 8) * 2;
    const uint32_t b_lo = ((uint32_t)(wn * 64 + (lane & 7) + ((lane >> 4) & 1) * 8) * APITCH
                          + ((lane >> 3) & 1) * 8) * 2;

    const int lr0 = tid >> 2, seg = tid & 3;

    // async tile fetch into buffer `buf` for K-chunk kc0
    auto issue = [&](int buf, int kc0) {
#pragma unroll
        for (int p = 0; p < 2; p++) {
            int row = lr0 + p * 64;
            int ar = m0 + row;
            uint32_t ad = asb + ((uint32_t)(buf * BM + row) * APITCH + seg * 8) * 2;
            const __half* as = A + (size_t)(ar < NN ? ar : 0) * K + kc0 + seg * 8;
            if (ar < NN) cp16(ad, as); else cp16z(ad, as);
            uint32_t bd = bsb + ((uint32_t)(buf * BN + row) * APITCH + seg * 8) * 2;
            cp16(bd, W + (size_t)(n0 + row) * K + kc0 + seg * 8);
        }
        cp_commit();
    };

    issue(0, 0);
    cp_wait0();
    __syncthreads();

    for (int it = 0; it < nit; ++it) {
        int cur = it & 1;
        if (it + 1 < nit) issue(1 - cur, (it + 1) * BK);
        uint32_t abase = asb + (uint32_t)cur * (BM * APITCH * 2) + a_lo;
        uint32_t bbase = bsb + (uint32_t)cur * (BN * APITCH * 2) + b_lo;
#pragma unroll
        for (int ks = 0; ks < 2; ks++) {
            uint32_t koff = (uint32_t)(ks * 16) * 2;
            uint32_t af[2][4], bf[8][2];
#pragma unroll
            for (int mi = 0; mi < 2; mi++)
                ldsm4(af[mi], abase + (uint32_t)(mi * 16 * APITCH * 2) + koff);
#pragma unroll
            for (int p = 0; p < 4; p++) {
                uint32_t tmp[4];
                ldsm4(tmp, bbase + (uint32_t)(p * 16 * APITCH * 2) + koff);
                bf[2 * p][0] = tmp[0]; bf[2 * p][1] = tmp[1];
                bf[2 * p + 1][0] = tmp[2]; bf[2 * p + 1][1] = tmp[3];
            }
#pragma unroll
            for (int mi = 0; mi < 2; mi++)
#pragma unroll
                for (int ni = 0; ni < 8; ni++)
                    mma16816(acc[mi][ni], af[mi], bf[ni]);
        }
        if (it + 1 < nit) {
            cp_wait0();
            __syncthreads();
        }
    }

    // epilogue: fp16 output, split cols <448 -> Cl, >=448 -> Cr
#pragma unroll
    for (int mi = 0; mi < 2; mi++) {
#pragma unroll
        for (int ni = 0; ni < 8; ni++) {
            int row = m0 + wm * 32 + mi * 16 + g;
            int cg = n0 + wn * 64 + ni * 8 + 2 * tg;
            __half* base = (cg < HC) ? Cl : Cr;
            int cc = (cg < HC) ? cg : cg - HC;
            if (row < NN)
                *(__half2*)&base[(size_t)row * HC + cc] =
                    __floats2half2_rn(acc[mi][ni][0], acc[mi][ni][1]);
            if (row + 8 < NN)
                *(__half2*)&base[(size_t)(row + 8) * HC + cc] =
                    __floats2half2_rn(acc[mi][ni][2], acc[mi][ni][3]);
        }
    }
}

// ---------------- fused GATv2 edge kernel: fp16 gathers, prefetch-pipelined -----
__global__ __launch_bounds__(128) void k_gat(const __half* __restrict__ xl,
                                             const __half* __restrict__ xr,
                                             const float* __restrict__ We,
                                             const float* __restrict__ att,
                                             const float* __restrict__ bias,
                                             const float* __restrict__ eattr,
                                             const int* __restrict__ ei,
                                             float* __restrict__ out,
                                             int apply_elu) {
    __shared__ int s_eid[1024];
    __shared__ int s_srt[1024];
    int dst = blockIdx.x;
    int t = threadIdx.x;
    int start = g_cs[dst];
    int deg = g_cs[dst + 1] - start;
    for (int i = t; i < deg; i += 128) s_eid[i] = g_eid[start + i];
    __syncthreads();
    for (int i = t; i < deg; i += 128) {
        int key = s_eid[i]; int r = 0;
        for (int j = 0; j < deg; j++) r += (s_eid[j] < key);
        s_srt[r] = key;
    }
    __syncthreads();

    int g = t >> 4, l = t & 15;
    bool act = (l < 14);
    int c0 = g * 56 + l * 4;
    float4 xr4 = make_float4(0, 0, 0, 0), att4 = make_float4(0, 0, 0, 0);
    float4 We4[DE];
    float4 acc = make_float4(0, 0, 0, 0);
    float wsum = 0.f;
    if (act) {
        uint2 u = *(const uint2*)&xr[(size_t)dst * HC + c0];
        float2 f0 = __half22float2(*(__half2*)&u.x);
        float2 f1 = __half22float2(*(__half2*)&u.y);
        xr4 = make_float4(f0.x, f0.y, f1.x, f1.y);
        att4 = *(const float4*)&att[c0];
#pragma unroll
        for (int d = 0; d < DE; d++) We4[d] = *(const float4*)&We[d * HC + c0];
    }

    uint2 xl_u = make_uint2(0u, 0u);
    float ea_nxt[DE] = {0.f, 0.f, 0.f, 0.f, 0.f};
    if (act && deg > 0) {
        int e = s_srt[0];
        int s; const float* ea;
        if (e < NE) { s = ei[e]; ea = eattr + (size_t)e * DE; }
        else        { s = dst;   ea = g_loop + (size_t)dst * DE; }
        xl_u = *(const uint2*)&xl[(size_t)s * HC + c0];
#pragma unroll
        for (int d = 0; d < DE; d++) ea_nxt[d] = ea[d];
    }

    for (int i = 0; i < deg; i++) {
        float2 f0 = __half22float2(*(__half2*)&xl_u.x);
        float2 f1 = __half22float2(*(__half2*)&xl_u.y);
        float4 xl4 = make_float4(f0.x, f0.y, f1.x, f1.y);
        float e0 = ea_nxt[0], e1 = ea_nxt[1], e2 = ea_nxt[2], e3 = ea_nxt[3], e4 = ea_nxt[4];
        if (act && i + 1 < deg) {          // prefetch next edge before the shfl chain
            int e = s_srt[i + 1];
            int s; const float* ea;
            if (e < NE) { s = ei[e]; ea = eattr + (size_t)e * DE; }
            else        { s = dst;   ea = g_loop + (size_t)dst * DE; }
            xl_u = *(const uint2*)&xl[(size_t)s * HC + c0];
#pragma unroll
            for (int d = 0; d < DE; d++) ea_nxt[d] = ea[d];
        }
        float partial = 0.f;
        if (act) {
            float sx = xl4.x + xr4.x + e0*We4[0].x + e1*We4[1].x + e2*We4[2].x + e3*We4[3].x + e4*We4[4].x;
            float sy = xl4.y + xr4.y + e0*We4[0].y + e1*We4[1].y + e2*We4[2].y + e3*We4[3].y + e4*We4[4].y;
            float sz = xl4.z + xr4.z + e0*We4[0].z + e1*We4[1].z + e2*We4[2].z + e3*We4[3].z + e4*We4[4].z;
            float sw = xl4.w + xr4.w + e0*We4[0].w + e1*We4[1].w + e2*We4[2].w + e3*We4[3].w + e4*We4[4].w;
            sx = (sx > 0.f) ? sx : NEG_SLOPE * sx;
            sy = (sy > 0.f) ? sy : NEG_SLOPE * sy;
            sz = (sz > 0.f) ? sz : NEG_SLOPE * sz;
            sw = (sw > 0.f) ? sw : NEG_SLOPE * sw;
            partial = att4.x*sx + att4.y*sy + att4.z*sz + att4.w*sw;
        }
        partial += __shfl_xor_sync(0xffffffffu, partial, 8);
        partial += __shfl_xor_sync(0xffffffffu, partial, 4);
        partial += __shfl_xor_sync(0xffffffffu, partial, 2);
        partial += __shfl_xor_sync(0xffffffffu, partial, 1);
        float w = expf(partial);
        if (act) {
            wsum += w;
            acc.x += w * xl4.x; acc.y += w * xl4.y;
            acc.z += w * xl4.z; acc.w += w * xl4.w;
        }
    }
    if (act) {
        float inv = 1.f / (wsum + 1e-16f);
        float4 b4 = *(const float4*)&bias[c0];
        float4 o;
        o.x = acc.x * inv + b4.x; o.y = acc.y * inv + b4.y;
        o.z = acc.z * inv + b4.z; o.w = acc.w * inv + b4.w;
        if (apply_elu) {
            o.x = (o.x > 0.f) ? o.x : expm1f(o.x);
            o.y = (o.y > 0.f) ? o.y : expm1f(o.y);
            o.z = (o.z > 0.f) ? o.z : expm1f(o.z);
            o.w = (o.w > 0.f) ? o.w : expm1f(o.w);
        }
        *(float4*)&out[(size_t)dst * HC + c0] = o;
    }
}

// ---------------- BatchNorm stats + coefficients ----------------
__global__ void k_bn_stats(const float* __restrict__ h) {
    int t = threadIdx.x;
    int r0 = blockIdx.x * 64;
    int rend = min(r0 + 64, NN);
    float s = 0.f, q = 0.f;
    for (int r = r0; r < rend; r++) {
        float v = h[(size_t)r * HC + t];
        s += v; q += v * v;
    }
    atomicAdd(&g_colsum[t], s);
    atomicAdd(&g_colsq[t], q);
}

__global__ void k_bn_coef(const float* __restrict__ gamma, const float* __restrict__ beta) {
    int t = threadIdx.x;
    if (t >= HC) return;
    float m = g_colsum[t] * (1.f / NN);
    float var = g_colsq[t] * (1.f / NN) - m * m;
    float sc = rsqrtf(var + EPS_BN) * gamma[t];
    g_scale[t] = sc;
    g_shift[t] = beta[t] - m * sc;
}

// ---------------- pooling ----------------
__global__ void k_gcount(const int* __restrict__ batch) {
    int i = blockIdx.x * blockDim.x + threadIdx.x;
    if (i < NN) atomicAdd(&g_gcnt[batch[i]], 1.f);
}

__global__ void k_pool_partial(const int* __restrict__ batch,
                               const float* __restrict__ h2) {
    int t = threadIdx.x;
    int r0 = blockIdx.x * 64;
    int rend = min(r0 + 64, NN);
    int g = -1; float acc = 0.f;
    for (int r = r0; r < rend; r++) {
        int bg = batch[r];
        if (bg != g) {
            if (g >= 0) atomicAdd(&g_pooled[g * HC + t], acc);
            g = bg; acc = 0.f;
        }
        acc += h2[(size_t)r * HC + t];
    }
    if (g >= 0) atomicAdd(&g_pooled[g * HC + t], acc);
}

// ---------------- final: mean, BN over 32 rows, linear(448->18), log_softmax ------
__global__ __launch_bounds__(512) void k_final(const float* __restrict__ gamma,
                                               const float* __restrict__ beta,
                                               const float* __restrict__ Wlin,
                                               const float* __restrict__ blin,
                                               float* __restrict__ out) {
    __shared__ float s_scale[HC];
    __shared__ float s_shift[HC];
    __shared__ float s_log[NG * 18];
    int t = threadIdx.x;
    for (int idx = t; idx < NG * HC; idx += 512) {
        int g = idx / HC;
        float c = fmaxf(g_gcnt[g], 1.f);
        g_pooled[idx] = g_pooled[idx] / c;
    }
    __syncthreads();
    if (t < HC) {
        float s = 0.f, q = 0.f;
        for (int g = 0; g < NG; g++) {
            float v = g_pooled[g * HC + t];
            s += v; q += v * v;
        }
        float m = s * (1.f / NG);
        float var = q * (1.f / NG) - m * m;
        float sc = rsqrtf(var + EPS_BN) * gamma[t];
        s_scale[t] = sc;
        s_shift[t] = beta[t] - m * sc;
    }
    __syncthreads();
    for (int o = t; o < NG * 18; o += 512) {
        int g = o / 18, j = o % 18;
        float acc = blin[j];
        for (int c = 0; c < HC; c++)
            acc += (g_pooled[g * HC + c] * s_scale[c] + s_shift[c]) * Wlin[c * 18 + j];
        s_log[o] = acc;
    }
    __syncthreads();
    if (t < NG) {
        float m = -1e30f;
        for (int j = 0; j < 18; j++) m = fmaxf(m, s_log[t * 18 + j]);
        float s = 0.f;
        for (int j = 0; j < 18; j++) s += expf(s_log[t * 18 + j] - m);
        float lse = m + logf(s);
        for (int j = 0; j < 18; j++) out[t * 18 + j] = s_log[t * 18 + j] - lse;
    }
}

// ---------------- host launcher ----------------
extern "C" void kernel_launch(void* const* d_in, const int* in_sizes, int n_in,
                              void* d_out, int out_size) {
    const float* x     = (const float*)d_in[0];
    const int*   ei    = (const int*)d_in[1];
    const float* eattr = (const float*)d_in[2];
    const int*   batch = (const int*)d_in[3];
    const float* Wl1   = (const float*)d_in[4];
    const float* Wr1   = (const float*)d_in[5];
    const float* We1   = (const float*)d_in[6];
    const float* att1  = (const float*)d_in[7];
    const float* bias1 = (const float*)d_in[8];
    const float* Wl2   = (const float*)d_in[9];
    const float* Wr2   = (const float*)d_in[10];
    const float* We2   = (const float*)d_in[11];
    const float* att2  = (const float*)d_in[12];
    const float* bias2 = (const float*)d_in[13];
    const float* gamma = (const float*)d_in[14];
    const float* beta  = (const float*)d_in[15];
    const float* Wlin  = (const float*)d_in[16];
    const float* blin  = (const float*)d_in[17];
    float* out = (float*)d_out;

    float *p_h, *p_h2;
    __half *p_xl, *p_xr, *p_a, *p_w;
    cudaGetSymbolAddress((void**)&p_xl, g_xl);
    cudaGetSymbolAddress((void**)&p_xr, g_xr);
    cudaGetSymbolAddress((void**)&p_h,  g_h);
    cudaGetSymbolAddress((void**)&p_h2, g_h2);
    cudaGetSymbolAddress((void**)&p_a,  g_af16);
    cudaGetSymbolAddress((void**)&p_w,  g_wt16);

    dim3 ggrid(2 * HC / BN, (NN + BM - 1) / BM);   // 7 x 157

    // layer-1 GEMM first (launch index 4 = ncu capture slot)
    k_zero<<<256, 256>>>();
    k_prep_w<<<(2 * HC * DIN + 255) / 256, 256>>>(Wl1, Wr1, DIN);
    k_prep_a1<<<(NN * DIN + 255) / 256, 256>>>(x);
    gemm_f16<<<ggrid, 256>>>(DIN, p_a, p_w, p_xl, p_xr);

    // graph prep
    k_deg<<<(NE + 255) / 256, 256>>>(ei);
    k_scan1<<<NBLK, SB>>>();
    k_scan2<<<1, 128>>>();
    k_scan3<<<NBLK, SB>>>();
    k_scatter<<<(NE2 + 255) / 256, 256>>>(ei);
    k_loopattr_csr<<<(NN + 7) / 8, 256>>>(eattr);

    // layer 1 aggregate
    k_gat<<<NN, 128>>>(p_xl, p_xr, We1, att1, bias1, eattr, ei, p_h, 1);
    // batchnorm coefs + layer-2 A prep (BN fused)
    k_bn_stats<<<(NN + 63) / 64, HC>>>(p_h);
    k_bn_coef<<<1, HC>>>(gamma, beta);
    k_prep_a2<<<(NN * HC + 255) / 256, 256>>>();
    // layer 2
    k_prep_w<<<(2 * HC * HC + 255) / 256, 256>>>(Wl2, Wr2, HC);
    gemm_f16<<<ggrid, 256>>>(HC, p_a, p_w, p_xl, p_xr);
    k_gat<<<NN, 128>>>(p_xl, p_xr, We2, att2, bias2, eattr, ei, p_h2, 0);
    // pool + head
    k_gcount<<<(NN + 255) / 256, 256>>>(batch);
    k_pool_partial<<<(NN + 63) / 64, HC>>>(batch, p_h2);
    k_final<<<1, 512>>>(gamma, beta, Wlin, blin, out);
}

// round 13
// speedup vs baseline: 2.0887x; 1.0437x over previous
#include <cuda_runtime.h>
#include <cuda_fp16.h>
#include <cstdint>
#include <cstddef>
#include <math.h>

#define NN   20000
#define NE   320000
#define NE2  340000
#define NG   32
#define NH   8
#define HC   448
#define DIN  32
#define DE   5
#define NEG_SLOPE 0.2f
#define EPS_BN 1e-5f

// ---------------- scratch (static device arrays: no allocation) ----------------
__device__ __half g_xl[NN * HC];          // fp16 transformed features
__device__ __half g_xr[NN * HC];
__device__ float g_h [NN * HC];
__device__ float g_h2[NN * HC];
__device__ float g_loop[NN * DE];
__device__ int   g_deg[NN];
__device__ int   g_cs[NN + 1];
__device__ int   g_cur[NN];
__device__ int   g_eid[NE2];
__device__ float g_colsum[HC];
__device__ float g_colsq[HC];
__device__ float g_pooled[NG * HC];
__device__ float g_gcnt[NG];
__device__ float g_scale[HC];
__device__ float g_shift[HC];
__device__ int   g_bsum[128];
__device__ int   g_boff[128];
__device__ __half g_af16[NN * HC];        // A in fp16, [NN][K]
__device__ __half g_wt16[2 * HC * HC];    // W^T in fp16, [896][K]

// ---------------- zero accumulators ----------------
__global__ void k_zero() {
    int i = blockIdx.x * blockDim.x + threadIdx.x;
    int st = gridDim.x * blockDim.x;
    for (int j = i; j < NN; j += st) g_deg[j] = 0;
    for (int j = i; j < HC; j += st) { g_colsum[j] = 0.f; g_colsq[j] = 0.f; }
    for (int j = i; j < NG * HC; j += st) g_pooled[j] = 0.f;
    for (int j = i; j < NG; j += st) g_gcnt[j] = 0.f;
}

// ---------------- degree ----------------
__global__ void k_deg(const int* __restrict__ ei) {
    int e = blockIdx.x * blockDim.x + threadIdx.x;
    if (e < NE) atomicAdd(&g_deg[ei[NE + e]], 1);
}

// ---------------- 3-kernel parallel exclusive scan of (deg+1) ----------------
#define SB 256
#define NBLK 79
__global__ void k_scan1() {
    int b = blockIdx.x, t = threadIdx.x;
    int idx = b * SB + t;
    int v = (idx < NN) ? g_deg[idx] + 1 : 0;
    int s = v;
#pragma unroll
    for (int o = 16; o >= 1; o >>= 1) s += __shfl_xor_sync(0xffffffffu, s, o);
    __shared__ int ws[8];
    if ((t & 31) == 0) ws[t >> 5] = s;
    __syncthreads();
    if (t == 0) {
        int tot = 0;
#pragma unroll
        for (int w = 0; w < 8; w++) tot += ws[w];
        g_bsum[b] = tot;
    }
}
__global__ void k_scan2() {
    __shared__ int sv[128];
    int t = threadIdx.x;
    int v = (t < NBLK) ? g_bsum[t] : 0;
    sv[t] = v;
    __syncthreads();
    for (int off = 1; off < 128; off <<= 1) {
        int u = (t >= off) ? sv[t - off] : 0;
        __syncthreads();
        sv[t] += u;
        __syncthreads();
    }
    if (t < NBLK) g_boff[t] = sv[t] - v;   // exclusive
    if (t == NBLK - 1) g_cs[NN] = sv[t];   // total
}
__global__ void k_scan3() {
    int b = blockIdx.x, t = threadIdx.x;
    int lane = t & 31, wid = t >> 5;
    int idx = b * SB + t;
    int v = (idx < NN) ? g_deg[idx] + 1 : 0;
    int inc = v;
#pragma unroll
    for (int o = 1; o < 32; o <<= 1) {
        int u = __shfl_up_sync(0xffffffffu, inc, o);
        if (lane >= o) inc += u;
    }
    __shared__ int ws[8];
    if (lane == 31) ws[wid] = inc;
    __syncthreads();
    if (wid == 0 && lane < 8) {
        int wv = ws[lane];
#pragma unroll
        for (int o = 1; o < 8; o <<= 1) {
            int u = __shfl_up_sync(0xffu, wv, o);
            if (lane >= o) wv += u;
        }
        ws[lane] = wv;
    }
    __syncthreads();
    int base = g_boff[b] + (wid > 0 ? ws[wid - 1] : 0);
    int ex = base + inc - v;
    if (idx < NN) { g_cs[idx] = ex; g_cur[idx] = ex; }
}

// ---------------- scatter edge ids into CSR buckets ----------------
__global__ void k_scatter(const int* __restrict__ ei) {
    int e = blockIdx.x * blockDim.x + threadIdx.x;
    if (e >= NE2) return;
    int d = (e < NE) ? ei[NE + e] : (e - NE);
    int pos = atomicAdd(&g_cur[d], 1);
    g_eid[pos] = e;
}

// ---------------- self-loop attr via CSR: one warp per node ----------------
__global__ void k_loopattr_csr(const float* __restrict__ eattr) {
    int w = blockIdx.x * 8 + (threadIdx.x >> 5);
    int lane = threadIdx.x & 31;
    if (w >= NN) return;
    int s0 = g_cs[w];
    int n = g_cs[w + 1] - s0;
    float a0 = 0.f, a1 = 0.f, a2 = 0.f, a3 = 0.f, a4 = 0.f;
    for (int i = lane; i < n; i += 32) {
        int e = g_eid[s0 + i];
        if (e < NE) {
            const float* p = eattr + (size_t)e * DE;
            a0 += p[0]; a1 += p[1]; a2 += p[2]; a3 += p[3]; a4 += p[4];
        }
    }
#pragma unroll
    for (int o = 16; o >= 1; o >>= 1) {
        a0 += __shfl_xor_sync(0xffffffffu, a0, o);
        a1 += __shfl_xor_sync(0xffffffffu, a1, o);
        a2 += __shfl_xor_sync(0xffffffffu, a2, o);
        a3 += __shfl_xor_sync(0xffffffffu, a3, o);
        a4 += __shfl_xor_sync(0xffffffffu, a4, o);
    }
    if (lane == 0) {
        float dg = fmaxf((float)g_deg[w], 1.f);
        g_loop[w * DE + 0] = a0 / dg;
        g_loop[w * DE + 1] = a1 / dg;
        g_loop[w * DE + 2] = a2 / dg;
        g_loop[w * DE + 3] = a3 / dg;
        g_loop[w * DE + 4] = a4 / dg;
    }
}

// ---------------- weight prep: W^T -> fp16, [896][K] ----------------
__global__ void k_prep_w(const float* __restrict__ Wl, const float* __restrict__ Wr, int K) {
    int i = blockIdx.x * blockDim.x + threadIdx.x;
    if (i >= 2 * HC * K) return;
    int n = i / K, k = i % K;
    float v = (n < HC) ? Wl[k * HC + n] : Wr[k * HC + (n - HC)];
    g_wt16[i] = __float2half(v);
}

// ---------------- A prep layer1: x -> fp16, [NN][32] ----------------
__global__ void k_prep_a1(const float* __restrict__ x) {
    int i = blockIdx.x * blockDim.x + threadIdx.x;
    if (i < NN * DIN) g_af16[i] = __float2half(x[i]);
}

// ---------------- A prep layer2: BN(h) fused -> fp16 ----------------
__global__ void k_prep_a2() {
    int i = blockIdx.x * blockDim.x + threadIdx.x;
    if (i >= NN * HC) return;
    int c = i % HC;
    g_af16[i] = __float2half(g_h[i] * g_scale[c] + g_shift[c]);
}

// ======================= fp16 mma.sync GEMM (ldmatrix + cp.async) ==============
#define BM 128
#define BN 128
#define BK 32
#define APITCH 40

__device__ __forceinline__ void mma16816(float* c, const uint32_t* a, const uint32_t* b) {
    asm volatile(
        "mma.sync.aligned.m16n8k16.row.col.f32.f16.f16.f32 "
        "{%0,%1,%2,%3}, {%4,%5,%6,%7}, {%8,%9}, {%0,%1,%2,%3};\n"
        : "+f"(c[0]), "+f"(c[1]), "+f"(c[2]), "+f"(c[3])
        : "r"(a[0]), "r"(a[1]), "r"(a[2]), "r"(a[3]), "r"(b[0]), "r"(b[1]));
}
__device__ __forceinline__ void ldsm4(uint32_t* r, uint32_t addr) {
    asm volatile("ldmatrix.sync.aligned.m8n8.x4.shared.b16 {%0,%1,%2,%3}, [%4];"
        : "=r"(r[0]), "=r"(r[1]), "=r"(r[2]), "=r"(r[3]) : "r"(addr));
}
__device__ __forceinline__ void cp16(uint32_t dst, const void* src) {
    asm volatile("cp.async.cg.shared.global [%0], [%1], 16;" :: "r"(dst), "l"(src));
}
__device__ __forceinline__ void cp16z(uint32_t dst, const void* src) {
    asm volatile("cp.async.cg.shared.global [%0], [%1], 16, 0;" :: "r"(dst), "l"(src));
}
__device__ __forceinline__ void cp_commit() { asm volatile("cp.async.commit_group;"); }
__device__ __forceinline__ void cp_wait0()  { asm volatile("cp.async.wait_group 0;" ::: "memory"); }

__global__ __launch_bounds__(256) void gemm_f16(int K,
                                                const __half* __restrict__ A,
                                                const __half* __restrict__ W,
                                                __half* __restrict__ Cl,
                                                __half* __restrict__ Cr) {
    __shared__ __half As[2][BM][APITCH];
    __shared__ __half Bs[2][BN][APITCH];
    const int tid = threadIdx.x, lane = tid & 31, wid = tid >> 5;
    const int wm = wid & 3, wn = wid >> 2;
    const int g = lane >> 2, tg = lane & 3;
    const int m0 = blockIdx.y * BM, n0 = blockIdx.x * BN;
    const int nit = K / BK;

    float acc[2][8][4];
#pragma unroll
    for (int mi = 0; mi < 2; mi++)
#pragma unroll
        for (int ni = 0; ni < 8; ni++)
#pragma unroll
            for (int r = 0; r < 4; r++) acc[mi][ni][r] = 0.f;

    const uint32_t asb = (uint32_t)__cvta_generic_to_shared(&As[0][0][0]);
    const uint32_t bsb = (uint32_t)__cvta_generic_to_shared(&Bs[0][0][0]);
    const uint32_t a_lo = ((uint32_t)(wm * 32 + (lane & 15)) * APITCH + (lane >> 4) * 8) * 2;
    const uint32_t b_lo = ((uint32_t)(wn * 64 + (lane & 7) + ((lane >> 4) & 1) * 8) * APITCH
                          + ((lane >> 3) & 1) * 8) * 2;

    const int lr0 = tid >> 2, seg = tid & 3;

    auto issue = [&](int buf, int kc0) {
#pragma unroll
        for (int p = 0; p < 2; p++) {
            int row = lr0 + p * 64;
            int ar = m0 + row;
            uint32_t ad = asb + ((uint32_t)(buf * BM + row) * APITCH + seg * 8) * 2;
            const __half* as = A + (size_t)(ar < NN ? ar : 0) * K + kc0 + seg * 8;
            if (ar < NN) cp16(ad, as); else cp16z(ad, as);
            uint32_t bd = bsb + ((uint32_t)(buf * BN + row) * APITCH + seg * 8) * 2;
            cp16(bd, W + (size_t)(n0 + row) * K + kc0 + seg * 8);
        }
        cp_commit();
    };

    issue(0, 0);
    cp_wait0();
    __syncthreads();

    for (int it = 0; it < nit; ++it) {
        int cur = it & 1;
        if (it + 1 < nit) issue(1 - cur, (it + 1) * BK);
        uint32_t abase = asb + (uint32_t)cur * (BM * APITCH * 2) + a_lo;
        uint32_t bbase = bsb + (uint32_t)cur * (BN * APITCH * 2) + b_lo;
#pragma unroll
        for (int ks = 0; ks < 2; ks++) {
            uint32_t koff = (uint32_t)(ks * 16) * 2;
            uint32_t af[2][4], bf[8][2];
#pragma unroll
            for (int mi = 0; mi < 2; mi++)
                ldsm4(af[mi], abase + (uint32_t)(mi * 16 * APITCH * 2) + koff);
#pragma unroll
            for (int p = 0; p < 4; p++) {
                uint32_t tmp[4];
                ldsm4(tmp, bbase + (uint32_t)(p * 16 * APITCH * 2) + koff);
                bf[2 * p][0] = tmp[0]; bf[2 * p][1] = tmp[1];
                bf[2 * p + 1][0] = tmp[2]; bf[2 * p + 1][1] = tmp[3];
            }
#pragma unroll
            for (int mi = 0; mi < 2; mi++)
#pragma unroll
                for (int ni = 0; ni < 8; ni++)
                    mma16816(acc[mi][ni], af[mi], bf[ni]);
        }
        if (it + 1 < nit) {
            cp_wait0();
            __syncthreads();
        }
    }

#pragma unroll
    for (int mi = 0; mi < 2; mi++) {
#pragma unroll
        for (int ni = 0; ni < 8; ni++) {
            int row = m0 + wm * 32 + mi * 16 + g;
            int cg = n0 + wn * 64 + ni * 8 + 2 * tg;
            __half* base = (cg < HC) ? Cl : Cr;
            int cc = (cg < HC) ? cg : cg - HC;
            if (row < NN)
                *(__half2*)&base[(size_t)row * HC + cc] =
                    __floats2half2_rn(acc[mi][ni][0], acc[mi][ni][1]);
            if (row + 8 < NN)
                *(__half2*)&base[(size_t)(row + 8) * HC + cc] =
                    __floats2half2_rn(acc[mi][ni][2], acc[mi][ni][3]);
        }
    }
}

// ---------------- fused GATv2 edge kernel: 2-way ILP edge unroll ----------------
__global__ __launch_bounds__(128) void k_gat(const __half* __restrict__ xl,
                                             const __half* __restrict__ xr,
                                             const float* __restrict__ We,
                                             const float* __restrict__ att,
                                             const float* __restrict__ bias,
                                             const float* __restrict__ eattr,
                                             const int* __restrict__ ei,
                                             float* __restrict__ out,
                                             int apply_elu) {
    __shared__ int s_eid[1024];
    __shared__ int s_srt[1024];
    int dst = blockIdx.x;
    int t = threadIdx.x;
    int start = g_cs[dst];
    int deg = g_cs[dst + 1] - start;
    for (int i = t; i < deg; i += 128) s_eid[i] = g_eid[start + i];
    __syncthreads();
    for (int i = t; i < deg; i += 128) {
        int key = s_eid[i]; int r = 0;
        for (int j = 0; j < deg; j++) r += (s_eid[j] < key);
        s_srt[r] = key;
    }
    __syncthreads();

    int g = t >> 4, l = t & 15;
    bool act = (l < 14);
    int c0 = g * 56 + l * 4;
    float4 xr4 = make_float4(0, 0, 0, 0), att4 = make_float4(0, 0, 0, 0);
    float4 We4[DE];
    float4 acc = make_float4(0, 0, 0, 0);
    float wsum = 0.f;
    if (act) {
        uint2 u = *(const uint2*)&xr[(size_t)dst * HC + c0];
        float2 f0 = __half22float2(*(__half2*)&u.x);
        float2 f1 = __half22float2(*(__half2*)&u.y);
        xr4 = make_float4(f0.x, f0.y, f1.x, f1.y);
        att4 = *(const float4*)&att[c0];
#pragma unroll
        for (int d = 0; d < DE; d++) We4[d] = *(const float4*)&We[d * HC + c0];
    }

    // edge data loader (gather xl + edge attr)
    auto lde = [&](int idx, uint2& u, float* ea) {
        int e = s_srt[idx];
        int s; const float* p;
        if (e < NE) { s = ei[e]; p = eattr + (size_t)e * DE; }
        else        { s = dst;   p = g_loop + (size_t)dst * DE; }
        u = *(const uint2*)&xl[(size_t)s * HC + c0];
#pragma unroll
        for (int d = 0; d < DE; d++) ea[d] = p[d];
    };
    auto score = [&](const uint2& u, const float* ea, float4& x4) -> float {
        float2 f0 = __half22float2(*(const __half2*)&u.x);
        float2 f1 = __half22float2(*(const __half2*)&u.y);
        x4 = make_float4(f0.x, f0.y, f1.x, f1.y);
        float sx = x4.x + xr4.x, sy = x4.y + xr4.y, sz = x4.z + xr4.z, sw = x4.w + xr4.w;
#pragma unroll
        for (int d = 0; d < DE; d++) {
            sx += ea[d] * We4[d].x; sy += ea[d] * We4[d].y;
            sz += ea[d] * We4[d].z; sw += ea[d] * We4[d].w;
        }
        sx = (sx > 0.f) ? sx : NEG_SLOPE * sx;
        sy = (sy > 0.f) ? sy : NEG_SLOPE * sy;
        sz = (sz > 0.f) ? sz : NEG_SLOPE * sz;
        sw = (sw > 0.f) ? sw : NEG_SLOPE * sw;
        return att4.x * sx + att4.y * sy + att4.z * sz + att4.w * sw;
    };

    uint2 ua = make_uint2(0u, 0u), ub = make_uint2(0u, 0u);
    float ea_a[DE] = {0, 0, 0, 0, 0}, ea_b[DE] = {0, 0, 0, 0, 0};
    if (act) {
        if (deg > 0) lde(0, ua, ea_a);
        if (deg > 1) lde(1, ub, ea_b);
    }

    int i = 0;
    for (; i + 1 < deg; i += 2) {
        uint2 ca = ua, cb = ub;
        float fa[DE], fb[DE];
#pragma unroll
        for (int d = 0; d < DE; d++) { fa[d] = ea_a[d]; fb[d] = ea_b[d]; }
        if (act) {  // prefetch next pair before the serial chains
            if (i + 2 < deg) lde(i + 2, ua, ea_a);
            if (i + 3 < deg) lde(i + 3, ub, ea_b);
        }
        float pa = 0.f, pb = 0.f;
        float4 xa = make_float4(0, 0, 0, 0), xb = make_float4(0, 0, 0, 0);
        if (act) {
            pa = score(ca, fa, xa);
            pb = score(cb, fb, xb);
        }
        // two independent shuffle chains, interleaved
        pa += __shfl_xor_sync(0xffffffffu, pa, 8);
        pb += __shfl_xor_sync(0xffffffffu, pb, 8);
        pa += __shfl_xor_sync(0xffffffffu, pa, 4);
        pb += __shfl_xor_sync(0xffffffffu, pb, 4);
        pa += __shfl_xor_sync(0xffffffffu, pa, 2);
        pb += __shfl_xor_sync(0xffffffffu, pb, 2);
        pa += __shfl_xor_sync(0xffffffffu, pa, 1);
        pb += __shfl_xor_sync(0xffffffffu, pb, 1);
        float wa = expf(pa), wb = expf(pb);
        if (act) {
            wsum += wa;
            acc.x += wa * xa.x; acc.y += wa * xa.y; acc.z += wa * xa.z; acc.w += wa * xa.w;
            wsum += wb;
            acc.x += wb * xb.x; acc.y += wb * xb.y; acc.z += wb * xb.z; acc.w += wb * xb.w;
        }
    }
    if (i < deg) {   // odd tail: edge i is in (ua, ea_a)
        float pa = 0.f;
        float4 xa = make_float4(0, 0, 0, 0);
        if (act) pa = score(ua, ea_a, xa);
        pa += __shfl_xor_sync(0xffffffffu, pa, 8);
        pa += __shfl_xor_sync(0xffffffffu, pa, 4);
        pa += __shfl_xor_sync(0xffffffffu, pa, 2);
        pa += __shfl_xor_sync(0xffffffffu, pa, 1);
        float wa = expf(pa);
        if (act) {
            wsum += wa;
            acc.x += wa * xa.x; acc.y += wa * xa.y; acc.z += wa * xa.z; acc.w += wa * xa.w;
        }
    }

    if (act) {
        float inv = 1.f / (wsum + 1e-16f);
        float4 b4 = *(const float4*)&bias[c0];
        float4 o;
        o.x = acc.x * inv + b4.x; o.y = acc.y * inv + b4.y;
        o.z = acc.z * inv + b4.z; o.w = acc.w * inv + b4.w;
        if (apply_elu) {
            o.x = (o.x > 0.f) ? o.x : expm1f(o.x);
            o.y = (o.y > 0.f) ? o.y : expm1f(o.y);
            o.z = (o.z > 0.f) ? o.z : expm1f(o.z);
            o.w = (o.w > 0.f) ? o.w : expm1f(o.w);
        }
        *(float4*)&out[(size_t)dst * HC + c0] = o;
    }
}

// ---------------- BatchNorm stats + coefficients ----------------
__global__ void k_bn_stats(const float* __restrict__ h) {
    int t = threadIdx.x;
    int r0 = blockIdx.x * 64;
    int rend = min(r0 + 64, NN);
    float s = 0.f, q = 0.f;
    for (int r = r0; r < rend; r++) {
        float v = h[(size_t)r * HC + t];
        s += v; q += v * v;
    }
    atomicAdd(&g_colsum[t], s);
    atomicAdd(&g_colsq[t], q);
}

__global__ void k_bn_coef(const float* __restrict__ gamma, const float* __restrict__ beta) {
    int t = threadIdx.x;
    if (t >= HC) return;
    float m = g_colsum[t] * (1.f / NN);
    float var = g_colsq[t] * (1.f / NN) - m * m;
    float sc = rsqrtf(var + EPS_BN) * gamma[t];
    g_scale[t] = sc;
    g_shift[t] = beta[t] - m * sc;
}

// ---------------- pooling (counts fused) ----------------
__global__ void k_pool_partial(const int* __restrict__ batch,
                               const float* __restrict__ h2) {
    int t = threadIdx.x;
    int r0 = blockIdx.x * 64;
    int rend = min(r0 + 64, NN);
    int g = -1; float acc = 0.f; int cnt = 0;
    for (int r = r0; r < rend; r++) {
        int bg = batch[r];
        if (bg != g) {
            if (g >= 0) {
                atomicAdd(&g_pooled[g * HC + t], acc);
                if (t == 0) atomicAdd(&g_gcnt[g], (float)cnt);
            }
            g = bg; acc = 0.f; cnt = 0;
        }
        acc += h2[(size_t)r * HC + t];
        cnt++;
    }
    if (g >= 0) {
        atomicAdd(&g_pooled[g * HC + t], acc);
        if (t == 0) atomicAdd(&g_gcnt[g], (float)cnt);
    }
}

// ---------------- final: mean, BN over 32 rows, linear(448->18), log_softmax ------
__global__ __launch_bounds__(512) void k_final(const float* __restrict__ gamma,
                                               const float* __restrict__ beta,
                                               const float* __restrict__ Wlin,
                                               const float* __restrict__ blin,
                                               float* __restrict__ out) {
    __shared__ float s_scale[HC];
    __shared__ float s_shift[HC];
    __shared__ float s_log[NG * 18];
    int t = threadIdx.x;
    for (int idx = t; idx < NG * HC; idx += 512) {
        int g = idx / HC;
        float c = fmaxf(g_gcnt[g], 1.f);
        g_pooled[idx] = g_pooled[idx] / c;
    }
    __syncthreads();
    if (t < HC) {
        float s = 0.f, q = 0.f;
        for (int g = 0; g < NG; g++) {
            float v = g_pooled[g * HC + t];
            s += v; q += v * v;
        }
        float m = s * (1.f / NG);
        float var = q * (1.f / NG) - m * m;
        float sc = rsqrtf(var + EPS_BN) * gamma[t];
        s_scale[t] = sc;
        s_shift[t] = beta[t] - m * sc;
    }
    __syncthreads();
    for (int o = t; o < NG * 18; o += 512) {
        int g = o / 18, j = o % 18;
        float acc = blin[j];
        for (int c = 0; c < HC; c++)
            acc += (g_pooled[g * HC + c] * s_scale[c] + s_shift[c]) * Wlin[c * 18 + j];
        s_log[o] = acc;
    }
    __syncthreads();
    if (t < NG) {
        float m = -1e30f;
        for (int j = 0; j < 18; j++) m = fmaxf(m, s_log[t * 18 + j]);
        float s = 0.f;
        for (int j = 0; j < 18; j++) s += expf(s_log[t * 18 + j] - m);
        float lse = m + logf(s);
        for (int j = 0; j < 18; j++) out[t * 18 + j] = s_log[t * 18 + j] - lse;
    }
}

// ---------------- host launcher ----------------
extern "C" void kernel_launch(void* const* d_in, const int* in_sizes, int n_in,
                              void* d_out, int out_size) {
    const float* x     = (const float*)d_in[0];
    const int*   ei    = (const int*)d_in[1];
    const float* eattr = (const float*)d_in[2];
    const int*   batch = (const int*)d_in[3];
    const float* Wl1   = (const float*)d_in[4];
    const float* Wr1   = (const float*)d_in[5];
    const float* We1   = (const float*)d_in[6];
    const float* att1  = (const float*)d_in[7];
    const float* bias1 = (const float*)d_in[8];
    const float* Wl2   = (const float*)d_in[9];
    const float* Wr2   = (const float*)d_in[10];
    const float* We2   = (const float*)d_in[11];
    const float* att2  = (const float*)d_in[12];
    const float* bias2 = (const float*)d_in[13];
    const float* gamma = (const float*)d_in[14];
    const float* beta  = (const float*)d_in[15];
    const float* Wlin  = (const float*)d_in[16];
    const float* blin  = (const float*)d_in[17];
    float* out = (float*)d_out;

    float *p_h, *p_h2;
    __half *p_xl, *p_xr, *p_a, *p_w;
    cudaGetSymbolAddress((void**)&p_xl, g_xl);
    cudaGetSymbolAddress((void**)&p_xr, g_xr);
    cudaGetSymbolAddress((void**)&p_h,  g_h);
    cudaGetSymbolAddress((void**)&p_h2, g_h2);
    cudaGetSymbolAddress((void**)&p_a,  g_af16);
    cudaGetSymbolAddress((void**)&p_w,  g_wt16);

    dim3 ggrid(2 * HC / BN, (NN + BM - 1) / BM);   // 7 x 157

    // layer-1 GEMM first (launch index 3 = ncu capture slot)
    k_zero<<<256, 256>>>();
    k_prep_w<<<(2 * HC * DIN + 255) / 256, 256>>>(Wl1, Wr1, DIN);
    k_prep_a1<<<(NN * DIN + 255) / 256, 256>>>(x);
    gemm_f16<<<ggrid, 256>>>(DIN, p_a, p_w, p_xl, p_xr);

    // graph prep
    k_deg<<<(NE + 255) / 256, 256>>>(ei);
    k_scan1<<<NBLK, SB>>>();
    k_scan2<<<1, 128>>>();
    k_scan3<<<NBLK, SB>>>();
    k_scatter<<<(NE2 + 255) / 256, 256>>>(ei);
    k_loopattr_csr<<<(NN + 7) / 8, 256>>>(eattr);

    // layer 1 aggregate
    k_gat<<<NN, 128>>>(p_xl, p_xr, We1, att1, bias1, eattr, ei, p_h, 1);
    // batchnorm coefs + layer-2 A prep (BN fused)
    k_bn_stats<<<(NN + 63) / 64, HC>>>(p_h);
    k_bn_coef<<<1, HC>>>(gamma, beta);
    k_prep_a2<<<(NN * HC + 255) / 256, 256>>>();
    // layer 2
    k_prep_w<<<(2 * HC * HC + 255) / 256, 256>>>(Wl2, Wr2, HC);
    gemm_f16<<<ggrid, 256>>>(HC, p_a, p_w, p_xl, p_xr);
    k_gat<<<NN, 128>>>(p_xl, p_xr, We2, att2, bias2, eattr, ei, p_h2, 0);
    // pool + head
    k_pool_partial<<<(NN + 63) / 64, HC>>>(batch, p_h2);
    k_final<<<1, 512>>>(gamma, beta, Wlin, blin, out);
}

// round 15
// speedup vs baseline: 2.0889x; 1.0001x over previous
#include <cuda_runtime.h>
#include <cuda_fp16.h>
#include <cstdint>
#include <cstddef>
#include <math.h>

#define NN   20000
#define NE   320000
#define NE2  340000
#define NG   32
#define NH   8
#define HC   448
#define DIN  32
#define DE   5
#define NEG_SLOPE 0.2f
#define EPS_BN 1e-5f

// ---------------- scratch (static device arrays: no allocation) ----------------
__device__ __half g_xl[NN * HC];          // fp16 transformed features
__device__ __half g_xr[NN * HC];
__device__ float g_h [NN * HC];
__device__ float g_h2[NN * HC];
__device__ float g_loop[NN * DE];
__device__ int   g_deg[NN];
__device__ int   g_cs[NN + 1];
__device__ int   g_cur[NN];
__device__ int   g_eid[NE2];
__device__ float g_colsum[HC];
__device__ float g_colsq[HC];
__device__ float g_pooled[NG * HC];
__device__ float g_gcnt[NG];
__device__ float g_scale[HC];
__device__ float g_shift[HC];
__device__ int   g_bsum[128];
__device__ int   g_boff[128];
__device__ __half g_af16[NN * HC];        // A in fp16, [NN][K]
__device__ __half g_wt16[2 * HC * HC];    // W^T in fp16, [896][K]

// ---------------- zero accumulators ----------------
__global__ void k_zero() {
    int i = blockIdx.x * blockDim.x + threadIdx.x;
    int st = gridDim.x * blockDim.x;
    for (int j = i; j < NN; j += st) g_deg[j] = 0;
    for (int j = i; j < HC; j += st) { g_colsum[j] = 0.f; g_colsq[j] = 0.f; }
    for (int j = i; j < NG * HC; j += st) g_pooled[j] = 0.f;
    for (int j = i; j < NG; j += st) g_gcnt[j] = 0.f;
}

// ---------------- degree ----------------
__global__ void k_deg(const int* __restrict__ ei) {
    int e = blockIdx.x * blockDim.x + threadIdx.x;
    if (e < NE) atomicAdd(&g_deg[ei[NE + e]], 1);
}

// ---------------- 3-kernel parallel exclusive scan of (deg+1) ----------------
#define SB 256
#define NBLK 79
__global__ void k_scan1() {
    int b = blockIdx.x, t = threadIdx.x;
    int idx = b * SB + t;
    int v = (idx < NN) ? g_deg[idx] + 1 : 0;
    int s = v;
#pragma unroll
    for (int o = 16; o >= 1; o >>= 1) s += __shfl_xor_sync(0xffffffffu, s, o);
    __shared__ int ws[8];
    if ((t & 31) == 0) ws[t >> 5] = s;
    __syncthreads();
    if (t == 0) {
        int tot = 0;
#pragma unroll
        for (int w = 0; w < 8; w++) tot += ws[w];
        g_bsum[b] = tot;
    }
}
__global__ void k_scan2() {
    __shared__ int sv[128];
    int t = threadIdx.x;
    int v = (t < NBLK) ? g_bsum[t] : 0;
    sv[t] = v;
    __syncthreads();
    for (int off = 1; off < 128; off <<= 1) {
        int u = (t >= off) ? sv[t - off] : 0;
        __syncthreads();
        sv[t] += u;
        __syncthreads();
    }
    if (t < NBLK) g_boff[t] = sv[t] - v;   // exclusive
    if (t == NBLK - 1) g_cs[NN] = sv[t];   // total
}
__global__ void k_scan3() {
    int b = blockIdx.x, t = threadIdx.x;
    int lane = t & 31, wid = t >> 5;
    int idx = b * SB + t;
    int v = (idx < NN) ? g_deg[idx] + 1 : 0;
    int inc = v;
#pragma unroll
    for (int o = 1; o < 32; o <<= 1) {
        int u = __shfl_up_sync(0xffffffffu, inc, o);
        if (lane >= o) inc += u;
    }
    __shared__ int ws[8];
    if (lane == 31) ws[wid] = inc;
    __syncthreads();
    if (wid == 0 && lane < 8) {
        int wv = ws[lane];
#pragma unroll
        for (int o = 1; o < 8; o <<= 1) {
            int u = __shfl_up_sync(0xffu, wv, o);
            if (lane >= o) wv += u;
        }
        ws[lane] = wv;
    }
    __syncthreads();
    int base = g_boff[b] + (wid > 0 ? ws[wid - 1] : 0);
    int ex = base + inc - v;
    if (idx < NN) { g_cs[idx] = ex; g_cur[idx] = ex; }
}

// ---------------- scatter edge ids into CSR buckets ----------------
__global__ void k_scatter(const int* __restrict__ ei) {
    int e = blockIdx.x * blockDim.x + threadIdx.x;
    if (e >= NE2) return;
    int d = (e < NE) ? ei[NE + e] : (e - NE);
    int pos = atomicAdd(&g_cur[d], 1);
    g_eid[pos] = e;
}

// ---------------- self-loop attr via CSR: one warp per node ----------------
__global__ void k_loopattr_csr(const float* __restrict__ eattr) {
    int w = blockIdx.x * 8 + (threadIdx.x >> 5);
    int lane = threadIdx.x & 31;
    if (w >= NN) return;
    int s0 = g_cs[w];
    int n = g_cs[w + 1] - s0;
    float a0 = 0.f, a1 = 0.f, a2 = 0.f, a3 = 0.f, a4 = 0.f;
    for (int i = lane; i < n; i += 32) {
        int e = g_eid[s0 + i];
        if (e < NE) {
            const float* p = eattr + (size_t)e * DE;
            a0 += p[0]; a1 += p[1]; a2 += p[2]; a3 += p[3]; a4 += p[4];
        }
    }
#pragma unroll
    for (int o = 16; o >= 1; o >>= 1) {
        a0 += __shfl_xor_sync(0xffffffffu, a0, o);
        a1 += __shfl_xor_sync(0xffffffffu, a1, o);
        a2 += __shfl_xor_sync(0xffffffffu, a2, o);
        a3 += __shfl_xor_sync(0xffffffffu, a3, o);
        a4 += __shfl_xor_sync(0xffffffffu, a4, o);
    }
    if (lane == 0) {
        float dg = fmaxf((float)g_deg[w], 1.f);
        g_loop[w * DE + 0] = a0 / dg;
        g_loop[w * DE + 1] = a1 / dg;
        g_loop[w * DE + 2] = a2 / dg;
        g_loop[w * DE + 3] = a3 / dg;
        g_loop[w * DE + 4] = a4 / dg;
    }
}

// ---------------- weight prep: W^T -> fp16, [896][K] ----------------
__global__ void k_prep_w(const float* __restrict__ Wl, const float* __restrict__ Wr, int K) {
    int i = blockIdx.x * blockDim.x + threadIdx.x;
    if (i >= 2 * HC * K) return;
    int n = i / K, k = i % K;
    float v = (n < HC) ? Wl[k * HC + n] : Wr[k * HC + (n - HC)];
    g_wt16[i] = __float2half(v);
}

// ---------------- A prep layer1: x -> fp16, [NN][32] ----------------
__global__ void k_prep_a1(const float* __restrict__ x) {
    int i = blockIdx.x * blockDim.x + threadIdx.x;
    if (i < NN * DIN) g_af16[i] = __float2half(x[i]);
}

// ---------------- A prep layer2: BN(h) fused -> fp16 ----------------
__global__ void k_prep_a2() {
    int i = blockIdx.x * blockDim.x + threadIdx.x;
    if (i >= NN * HC) return;
    int c = i % HC;
    g_af16[i] = __float2half(g_h[i] * g_scale[c] + g_shift[c]);
}

// ======================= fp16 mma.sync GEMM (BN=64, 3 blocks/SM) ===============
#define BM 128
#define BN 64
#define BK 32
#define APITCH 40

__device__ __forceinline__ void mma16816(float* c, const uint32_t* a, const uint32_t* b) {
    asm volatile(
        "mma.sync.aligned.m16n8k16.row.col.f32.f16.f16.f32 "
        "{%0,%1,%2,%3}, {%4,%5,%6,%7}, {%8,%9}, {%0,%1,%2,%3};\n"
        : "+f"(c[0]), "+f"(c[1]), "+f"(c[2]), "+f"(c[3])
        : "r"(a[0]), "r"(a[1]), "r"(a[2]), "r"(a[3]), "r"(b[0]), "r"(b[1]));
}
__device__ __forceinline__ void ldsm4(uint32_t* r, uint32_t addr) {
    asm volatile("ldmatrix.sync.aligned.m8n8.x4.shared.b16 {%0,%1,%2,%3}, [%4];"
        : "=r"(r[0]), "=r"(r[1]), "=r"(r[2]), "=r"(r[3]) : "r"(addr));
}
__device__ __forceinline__ void cp16(uint32_t dst, const void* src) {
    asm volatile("cp.async.cg.shared.global [%0], [%1], 16;" :: "r"(dst), "l"(src));
}
__device__ __forceinline__ void cp16z(uint32_t dst, const void* src) {
    asm volatile("cp.async.cg.shared.global [%0], [%1], 16, 0;" :: "r"(dst), "l"(src));
}
__device__ __forceinline__ void cp_commit() { asm volatile("cp.async.commit_group;"); }
__device__ __forceinline__ void cp_wait0()  { asm volatile("cp.async.wait_group 0;" ::: "memory"); }

__global__ __launch_bounds__(256, 3) void gemm_f16(int K,
                                                   const __half* __restrict__ A,
                                                   const __half* __restrict__ W,
                                                   __half* __restrict__ Cl,
                                                   __half* __restrict__ Cr) {
    __shared__ __half As[2][BM][APITCH];
    __shared__ __half Bs[2][BN][APITCH];
    const int tid = threadIdx.x, lane = tid & 31, wid = tid >> 5;
    const int wm = wid & 3, wn = wid >> 2;       // 4 x 2 warp grid, warp tile 32x32
    const int g = lane >> 2, tg = lane & 3;
    const int m0 = blockIdx.y * BM, n0 = blockIdx.x * BN;
    const int nit = K / BK;

    float acc[2][4][4];
#pragma unroll
    for (int mi = 0; mi < 2; mi++)
#pragma unroll
        for (int ni = 0; ni < 4; ni++)
#pragma unroll
            for (int r = 0; r < 4; r++) acc[mi][ni][r] = 0.f;

    const uint32_t asb = (uint32_t)__cvta_generic_to_shared(&As[0][0][0]);
    const uint32_t bsb = (uint32_t)__cvta_generic_to_shared(&Bs[0][0][0]);
    const uint32_t a_lo = ((uint32_t)(wm * 32 + (lane & 15)) * APITCH + (lane >> 4) * 8) * 2;
    const uint32_t b_lo = ((uint32_t)(wn * 32 + (lane & 7) + ((lane >> 4) & 1) * 8) * APITCH
                          + ((lane >> 3) & 1) * 8) * 2;

    const int lr0 = tid >> 2, seg = tid & 3;     // A rows lr0, lr0+64; B row lr0 (0..63)

    auto issue = [&](int buf, int kc0) {
#pragma unroll
        for (int p = 0; p < 2; p++) {
            int row = lr0 + p * 64;
            int ar = m0 + row;
            uint32_t ad = asb + ((uint32_t)(buf * BM + row) * APITCH + seg * 8) * 2;
            const __half* as = A + (size_t)(ar < NN ? ar : 0) * K + kc0 + seg * 8;
            if (ar < NN) cp16(ad, as); else cp16z(ad, as);
        }
        if (lr0 < BN) {
            uint32_t bd = bsb + ((uint32_t)(buf * BN + lr0) * APITCH + seg * 8) * 2;
            cp16(bd, W + (size_t)(n0 + lr0) * K + kc0 + seg * 8);
        }
        cp_commit();
    };

    issue(0, 0);
    cp_wait0();
    __syncthreads();

    for (int it = 0; it < nit; ++it) {
        int cur = it & 1;
        if (it + 1 < nit) issue(1 - cur, (it + 1) * BK);
        uint32_t abase = asb + (uint32_t)cur * (BM * APITCH * 2) + a_lo;
        uint32_t bbase = bsb + (uint32_t)cur * (BN * APITCH * 2) + b_lo;
#pragma unroll
        for (int ks = 0; ks < 2; ks++) {
            uint32_t koff = (uint32_t)(ks * 16) * 2;
            uint32_t af[2][4], bf[4][2];
#pragma unroll
            for (int mi = 0; mi < 2; mi++)
                ldsm4(af[mi], abase + (uint32_t)(mi * 16 * APITCH * 2) + koff);
#pragma unroll
            for (int p = 0; p < 2; p++) {
                uint32_t tmp[4];
                ldsm4(tmp, bbase + (uint32_t)(p * 16 * APITCH * 2) + koff);
                bf[2 * p][0] = tmp[0]; bf[2 * p][1] = tmp[1];
                bf[2 * p + 1][0] = tmp[2]; bf[2 * p + 1][1] = tmp[3];
            }
#pragma unroll
            for (int mi = 0; mi < 2; mi++)
#pragma unroll
                for (int ni = 0; ni < 4; ni++)
                    mma16816(acc[mi][ni], af[mi], bf[ni]);
        }
        if (it + 1 < nit) {
            cp_wait0();
            __syncthreads();
        }
    }

#pragma unroll
    for (int mi = 0; mi < 2; mi++) {
#pragma unroll
        for (int ni = 0; ni < 4; ni++) {
            int row = m0 + wm * 32 + mi * 16 + g;
            int cg = n0 + wn * 32 + ni * 8 + 2 * tg;
            __half* base = (cg < HC) ? Cl : Cr;
            int cc = (cg < HC) ? cg : cg - HC;
            if (row < NN)
                *(__half2*)&base[(size_t)row * HC + cc] =
                    __floats2half2_rn(acc[mi][ni][0], acc[mi][ni][1]);
            if (row + 8 < NN)
                *(__half2*)&base[(size_t)(row + 8) * HC + cc] =
                    __floats2half2_rn(acc[mi][ni][2], acc[mi][ni][3]);
        }
    }
}

// ---------------- fused GATv2 edge kernel: 2-way ILP edge unroll ----------------
__global__ __launch_bounds__(128) void k_gat(const __half* __restrict__ xl,
                                             const __half* __restrict__ xr,
                                             const float* __restrict__ We,
                                             const float* __restrict__ att,
                                             const float* __restrict__ bias,
                                             const float* __restrict__ eattr,
                                             const int* __restrict__ ei,
                                             float* __restrict__ out,
                                             int apply_elu) {
    __shared__ int s_eid[1024];
    __shared__ int s_srt[1024];
    int dst = blockIdx.x;
    int t = threadIdx.x;
    int start = g_cs[dst];
    int deg = g_cs[dst + 1] - start;
    for (int i = t; i < deg; i += 128) s_eid[i] = g_eid[start + i];
    __syncthreads();
    for (int i = t; i < deg; i += 128) {
        int key = s_eid[i]; int r = 0;
        for (int j = 0; j < deg; j++) r += (s_eid[j] < key);
        s_srt[r] = key;
    }
    __syncthreads();

    int g = t >> 4, l = t & 15;
    bool act = (l < 14);
    int c0 = g * 56 + l * 4;
    float4 xr4 = make_float4(0, 0, 0, 0), att4 = make_float4(0, 0, 0, 0);
    float4 We4[DE];
    float4 acc = make_float4(0, 0, 0, 0);
    float wsum = 0.f;
    if (act) {
        uint2 u = *(const uint2*)&xr[(size_t)dst * HC + c0];
        float2 f0 = __half22float2(*(__half2*)&u.x);
        float2 f1 = __half22float2(*(__half2*)&u.y);
        xr4 = make_float4(f0.x, f0.y, f1.x, f1.y);
        att4 = *(const float4*)&att[c0];
#pragma unroll
        for (int d = 0; d < DE; d++) We4[d] = *(const float4*)&We[d * HC + c0];
    }

    auto lde = [&](int idx, uint2& u, float* ea) {
        int e = s_srt[idx];
        int s; const float* p;
        if (e < NE) { s = ei[e]; p = eattr + (size_t)e * DE; }
        else        { s = dst;   p = g_loop + (size_t)dst * DE; }
        u = *(const uint2*)&xl[(size_t)s * HC + c0];
#pragma unroll
        for (int d = 0; d < DE; d++) ea[d] = p[d];
    };
    auto score = [&](const uint2& u, const float* ea, float4& x4) -> float {
        float2 f0 = __half22float2(*(const __half2*)&u.x);
        float2 f1 = __half22float2(*(const __half2*)&u.y);
        x4 = make_float4(f0.x, f0.y, f1.x, f1.y);
        float sx = x4.x + xr4.x, sy = x4.y + xr4.y, sz = x4.z + xr4.z, sw = x4.w + xr4.w;
#pragma unroll
        for (int d = 0; d < DE; d++) {
            sx += ea[d] * We4[d].x; sy += ea[d] * We4[d].y;
            sz += ea[d] * We4[d].z; sw += ea[d] * We4[d].w;
        }
        sx = (sx > 0.f) ? sx : NEG_SLOPE * sx;
        sy = (sy > 0.f) ? sy : NEG_SLOPE * sy;
        sz = (sz > 0.f) ? sz : NEG_SLOPE * sz;
        sw = (sw > 0.f) ? sw : NEG_SLOPE * sw;
        return att4.x * sx + att4.y * sy + att4.z * sz + att4.w * sw;
    };

    uint2 ua = make_uint2(0u, 0u), ub = make_uint2(0u, 0u);
    float ea_a[DE] = {0, 0, 0, 0, 0}, ea_b[DE] = {0, 0, 0, 0, 0};
    if (act) {
        if (deg > 0) lde(0, ua, ea_a);
        if (deg > 1) lde(1, ub, ea_b);
    }

    int i = 0;
    for (; i + 1 < deg; i += 2) {
        uint2 ca = ua, cb = ub;
        float fa[DE], fb[DE];
#pragma unroll
        for (int d = 0; d < DE; d++) { fa[d] = ea_a[d]; fb[d] = ea_b[d]; }
        if (act) {
            if (i + 2 < deg) lde(i + 2, ua, ea_a);
            if (i + 3 < deg) lde(i + 3, ub, ea_b);
        }
        float pa = 0.f, pb = 0.f;
        float4 xa = make_float4(0, 0, 0, 0), xb = make_float4(0, 0, 0, 0);
        if (act) {
            pa = score(ca, fa, xa);
            pb = score(cb, fb, xb);
        }
        pa += __shfl_xor_sync(0xffffffffu, pa, 8);
        pb += __shfl_xor_sync(0xffffffffu, pb, 8);
        pa += __shfl_xor_sync(0xffffffffu, pa, 4);
        pb += __shfl_xor_sync(0xffffffffu, pb, 4);
        pa += __shfl_xor_sync(0xffffffffu, pa, 2);
        pb += __shfl_xor_sync(0xffffffffu, pb, 2);
        pa += __shfl_xor_sync(0xffffffffu, pa, 1);
        pb += __shfl_xor_sync(0xffffffffu, pb, 1);
        float wa = expf(pa), wb = expf(pb);
        if (act) {
            wsum += wa;
            acc.x += wa * xa.x; acc.y += wa * xa.y; acc.z += wa * xa.z; acc.w += wa * xa.w;
            wsum += wb;
            acc.x += wb * xb.x; acc.y += wb * xb.y; acc.z += wb * xb.z; acc.w += wb * xb.w;
        }
    }
    if (i < deg) {
        float pa = 0.f;
        float4 xa = make_float4(0, 0, 0, 0);
        if (act) pa = score(ua, ea_a, xa);
        pa += __shfl_xor_sync(0xffffffffu, pa, 8);
        pa += __shfl_xor_sync(0xffffffffu, pa, 4);
        pa += __shfl_xor_sync(0xffffffffu, pa, 2);
        pa += __shfl_xor_sync(0xffffffffu, pa, 1);
        float wa = expf(pa);
        if (act) {
            wsum += wa;
            acc.x += wa * xa.x; acc.y += wa * xa.y; acc.z += wa * xa.z; acc.w += wa * xa.w;
        }
    }

    if (act) {
        float inv = 1.f / (wsum + 1e-16f);
        float4 b4 = *(const float4*)&bias[c0];
        float4 o;
        o.x = acc.x * inv + b4.x; o.y = acc.y * inv + b4.y;
        o.z = acc.z * inv + b4.z; o.w = acc.w * inv + b4.w;
        if (apply_elu) {
            o.x = (o.x > 0.f) ? o.x : expm1f(o.x);
            o.y = (o.y > 0.f) ? o.y : expm1f(o.y);
            o.z = (o.z > 0.f) ? o.z : expm1f(o.z);
            o.w = (o.w > 0.f) ? o.w : expm1f(o.w);
        }
        *(float4*)&out[(size_t)dst * HC + c0] = o;
    }
}

// ---------------- BatchNorm stats + coefficients ----------------
__global__ void k_bn_stats(const float* __restrict__ h) {
    int t = threadIdx.x;
    int r0 = blockIdx.x * 64;
    int rend = min(r0 + 64, NN);
    float s = 0.f, q = 0.f;
    for (int r = r0; r < rend; r++) {
        float v = h[(size_t)r * HC + t];
        s += v; q += v * v;
    }
    atomicAdd(&g_colsum[t], s);
    atomicAdd(&g_colsq[t], q);
}

__global__ void k_bn_coef(const float* __restrict__ gamma, const float* __restrict__ beta) {
    int t = threadIdx.x;
    if (t >= HC) return;
    float m = g_colsum[t] * (1.f / NN);
    float var = g_colsq[t] * (1.f / NN) - m * m;
    float sc = rsqrtf(var + EPS_BN) * gamma[t];
    g_scale[t] = sc;
    g_shift[t] = beta[t] - m * sc;
}

// ---------------- pooling (counts fused) ----------------
__global__ void k_pool_partial(const int* __restrict__ batch,
                               const float* __restrict__ h2) {
    int t = threadIdx.x;
    int r0 = blockIdx.x * 64;
    int rend = min(r0 + 64, NN);
    int g = -1; float acc = 0.f; int cnt = 0;
    for (int r = r0; r < rend; r++) {
        int bg = batch[r];
        if (bg != g) {
            if (g >= 0) {
                atomicAdd(&g_pooled[g * HC + t], acc);
                if (t == 0) atomicAdd(&g_gcnt[g], (float)cnt);
            }
            g = bg; acc = 0.f; cnt = 0;
        }
        acc += h2[(size_t)r * HC + t];
        cnt++;
    }
    if (g >= 0) {
        atomicAdd(&g_pooled[g * HC + t], acc);
        if (t == 0) atomicAdd(&g_gcnt[g], (float)cnt);
    }
}

// ---------------- final: mean, BN over 32 rows, linear(448->18), log_softmax ------
__global__ __launch_bounds__(512) void k_final(const float* __restrict__ gamma,
                                               const float* __restrict__ beta,
                                               const float* __restrict__ Wlin,
                                               const float* __restrict__ blin,
                                               float* __restrict__ out) {
    __shared__ float s_scale[HC];
    __shared__ float s_shift[HC];
    __shared__ float s_log[NG * 18];
    int t = threadIdx.x;
    for (int idx = t; idx < NG * HC; idx += 512) {
        int g = idx / HC;
        float c = fmaxf(g_gcnt[g], 1.f);
        g_pooled[idx] = g_pooled[idx] / c;
    }
    __syncthreads();
    if (t < HC) {
        float s = 0.f, q = 0.f;
        for (int g = 0; g < NG; g++) {
            float v = g_pooled[g * HC + t];
            s += v; q += v * v;
        }
        float m = s * (1.f / NG);
        float var = q * (1.f / NG) - m * m;
        float sc = rsqrtf(var + EPS_BN) * gamma[t];
        s_scale[t] = sc;
        s_shift[t] = beta[t] - m * sc;
    }
    __syncthreads();
    for (int o = t; o < NG * 18; o += 512) {
        int g = o / 18, j = o % 18;
        float acc = blin[j];
        for (int c = 0; c < HC; c++)
            acc += (g_pooled[g * HC + c] * s_scale[c] + s_shift[c]) * Wlin[c * 18 + j];
        s_log[o] = acc;
    }
    __syncthreads();
    if (t < NG) {
        float m = -1e30f;
        for (int j = 0; j < 18; j++) m = fmaxf(m, s_log[t * 18 + j]);
        float s = 0.f;
        for (int j = 0; j < 18; j++) s += expf(s_log[t * 18 + j] - m);
        float lse = m + logf(s);
        for (int j = 0; j < 18; j++) out[t * 18 + j] = s_log[t * 18 + j] - lse;
    }
}

// ---------------- host launcher ----------------
extern "C" void kernel_launch(void* const* d_in, const int* in_sizes, int n_in,
                              void* d_out, int out_size) {
    const float* x     = (const float*)d_in[0];
    const int*   ei    = (const int*)d_in[1];
    const float* eattr = (const float*)d_in[2];
    const int*   batch = (const int*)d_in[3];
    const float* Wl1   = (const float*)d_in[4];
    const float* Wr1   = (const float*)d_in[5];
    const float* We1   = (const float*)d_in[6];
    const float* att1  = (const float*)d_in[7];
    const float* bias1 = (const float*)d_in[8];
    const float* Wl2   = (const float*)d_in[9];
    const float* Wr2   = (const float*)d_in[10];
    const float* We2   = (const float*)d_in[11];
    const float* att2  = (const float*)d_in[12];
    const float* bias2 = (const float*)d_in[13];
    const float* gamma = (const float*)d_in[14];
    const float* beta  = (const float*)d_in[15];
    const float* Wlin  = (const float*)d_in[16];
    const float* blin  = (const float*)d_in[17];
    float* out = (float*)d_out;

    float *p_h, *p_h2;
    __half *p_xl, *p_xr, *p_a, *p_w;
    cudaGetSymbolAddress((void**)&p_xl, g_xl);
    cudaGetSymbolAddress((void**)&p_xr, g_xr);
    cudaGetSymbolAddress((void**)&p_h,  g_h);
    cudaGetSymbolAddress((void**)&p_h2, g_h2);
    cudaGetSymbolAddress((void**)&p_a,  g_af16);
    cudaGetSymbolAddress((void**)&p_w,  g_wt16);

    dim3 ggrid(2 * HC / BN, (NN + BM - 1) / BM);   // 14 x 157

    // layer-1 GEMM first (capture slot)
    k_zero<<<256, 256>>>();
    k_prep_w<<<(2 * HC * DIN + 255) / 256, 256>>>(Wl1, Wr1, DIN);
    k_prep_a1<<<(NN * DIN + 255) / 256, 256>>>(x);
    gemm_f16<<<ggrid, 256>>>(DIN, p_a, p_w, p_xl, p_xr);

    // graph prep
    k_deg<<<(NE + 255) / 256, 256>>>(ei);
    k_scan1<<<NBLK, SB>>>();
    k_scan2<<<1, 128>>>();
    k_scan3<<<NBLK, SB>>>();
    k_scatter<<<(NE2 + 255) / 256, 256>>>(ei);
    k_loopattr_csr<<<(NN + 7) / 8, 256>>>(eattr);

    // layer 1 aggregate
    k_gat<<<NN, 128>>>(p_xl, p_xr, We1, att1, bias1, eattr, ei, p_h, 1);
    // batchnorm coefs + layer-2 A prep (BN fused)
    k_bn_stats<<<(NN + 63) / 64, HC>>>(p_h);
    k_bn_coef<<<1, HC>>>(gamma, beta);
    k_prep_a2<<<(NN * HC + 255) / 256, 256>>>();
    // layer 2
    k_prep_w<<<(2 * HC * HC + 255) / 256, 256>>>(Wl2, Wr2, HC);
    gemm_f16<<<ggrid, 256>>>(HC, p_a, p_w, p_xl, p_xr);
    k_gat<<<NN, 128>>>(p_xl, p_xr, We2, att2, bias2, eattr, ei, p_h2, 0);
    // pool + head
    k_pool_partial<<<(NN + 63) / 64, HC>>>(batch, p_h2);
    k_final<<<1, 512>>>(gamma, beta, Wlin, blin, out);
}